// round 13
// baseline (speedup 1.0000x reference)
#include <cuda_runtime.h>

#define NN 30000
#define NE 480000
#define CH 64
#define NHEADS 4
#define KZ 256          // 64 channels x 4 heads
#define SCAN_BLOCKS ((NN + 255) / 256)   // 118
#define GEMM_BLOCKS ((NN + 127) / 128)   // 235

typedef unsigned long long ull;

// ---------------- f32x2 helpers (sm_103a packed fp32 pipe) ----------------
__device__ __forceinline__ ull pk2(float lo, float hi) {
    ull r;
    asm("mov.b64 %0, {%1, %2};" : "=l"(r) : "f"(lo), "f"(hi));
    return r;
}
__device__ __forceinline__ void upk2(float& lo, float& hi, ull v) {
    asm("mov.b64 {%0, %1}, %2;" : "=f"(lo), "=f"(hi) : "l"(v));
}
__device__ __forceinline__ ull fma2(ull a, ull b, ull c) {
    ull d;
    asm("fma.rn.f32x2 %0, %1, %2, %3;" : "=l"(d) : "l"(a), "l"(b), "l"(c));
    return d;
}
__device__ __forceinline__ ull mul2(ull a, ull b) {
    ull d;
    asm("mul.rn.f32x2 %0, %1, %2;" : "=l"(d) : "l"(a), "l"(b));
    return d;
}

// ---------------- scratch (device globals; no allocations allowed) ----------------
__device__ __align__(16) float g_L[NN * 4];        // per-node head logits
__device__ __align__(16) float g_attnP[NE * 4];    // per-edge attention, CSR order
__device__ __align__(16) float g_Z[NN * KZ];       // aggregated weighted features [node][c*4+m]
__device__ __align__(16) float g_H[NN * CH];       // relu(conv) output between layers
__device__ __align__(16) float g_Wp[KZ * CH];      // permuted weight for current layer
__device__ int   g_deg[NN];                        // zeroed at module load; re-zeroed by k_gemm L0
__device__ int   g_rowptr[NN];                     // block-local exclusive prefix
__device__ int   g_wptr[NN];                       // block-local write cursor
__device__ int   g_srcP[NE];                       // src node per CSR position
__device__ int   g_dstP[NE];                       // dst node per CSR position
__device__ int   g_bsum[SCAN_BLOCKS];
__device__ int   g_boff[SCAN_BLOCKS];              // per-256-node-block global offset
__device__ int   g_ctr;                            // scan completion counter (self-resetting)
__device__ float g_bnp[GEMM_BLOCKS * CH];
__device__ float g_bnp2[GEMM_BLOCKS * CH];
__device__ float g_scale[CH];
__device__ float g_shift[CH];

// ---------------- CSR build ----------------
__global__ void k_count(const int* __restrict__ dstE) {
    int g = blockIdx.x * blockDim.x + threadIdx.x;
    int e = 2 * g;
    if (e < NE) {
        int2 d = *(const int2*)(dstE + e);
        atomicAdd(&g_deg[d.x], 1);
        atomicAdd(&g_deg[d.y], 1);
    }
}

// fused scan: per-block local scan; last block scans the 118 block sums.
__global__ void k_scan() {
    int b = blockIdx.x, t = threadIdx.x;
    int i = b * 256 + t;
    int v = (i < NN) ? g_deg[i] : 0;
    int lane = t & 31, wid = t >> 5;
    int x = v;
    #pragma unroll
    for (int off = 1; off < 32; off <<= 1) {
        int y = __shfl_up_sync(0xFFFFFFFFu, x, off);
        if (lane >= off) x += y;
    }
    __shared__ int wsum[8];
    __shared__ int sIsLast;
    if (lane == 31) wsum[wid] = x;
    __syncthreads();
    if (wid == 0) {
        int s = (lane < 8) ? wsum[lane] : 0;
        #pragma unroll
        for (int off = 1; off < 8; off <<= 1) {
            int y = __shfl_up_sync(0xFFFFFFFFu, s, off);
            if (lane >= off) s += y;
        }
        if (lane < 8) wsum[lane] = s;   // inclusive warp sums
    }
    __syncthreads();
    int base = (wid > 0) ? wsum[wid - 1] : 0;
    int excl = base + x - v;
    if (i < NN) { g_rowptr[i] = excl; g_wptr[i] = excl; }
    if (t == 255) g_bsum[b] = base + x;

    // last block scans the block sums into g_boff
    __threadfence();   // tiny kernel: L1 flush harmless here
    __syncthreads();
    if (t == 0) sIsLast = (atomicAdd(&g_ctr, 1) == (int)gridDim.x - 1);
    __syncthreads();
    if (sIsLast) {
        int v2 = (t < SCAN_BLOCKS) ? g_bsum[t] : 0;
        int x2 = v2;
        #pragma unroll
        for (int off = 1; off < 32; off <<= 1) {
            int y = __shfl_up_sync(0xFFFFFFFFu, x2, off);
            if (lane >= off) x2 += y;
        }
        __shared__ int ws2[8];
        if (lane == 31) ws2[wid] = x2;
        __syncthreads();
        if (t == 0) {
            int a = 0;
            #pragma unroll
            for (int wv = 0; wv < 8; wv++) { int tmp = ws2[wv]; ws2[wv] = a; a += tmp; }
            g_ctr = 0;   // self-reset for next replay
        }
        __syncthreads();
        if (t < SCAN_BLOCKS) g_boff[t] = ws2[wid] + x2 - v2;
    }
}

__global__ void k_scatter(const int* __restrict__ srcE, const int* __restrict__ dstE) {
    int e = blockIdx.x * blockDim.x + threadIdx.x;
    if (e < NE) {
        int s = srcE[e];
        int d = dstE[e];
        int p = atomicAdd(&g_wptr[d], 1) + g_boff[d >> 8];
        g_srcP[p] = s;
        g_dstP[p] = d;
    }
}

// ---------------- per-node head logits (tiled): L[n][m] = xhat[n]@U[m] ----------------
// 128 nodes/block, BN folded into U' = U*sc and constant cU[m] = sum_k sh[k]*U[m][k].
__global__ void __launch_bounds__(256) k_L(const float* __restrict__ X,
                                           const float* __restrict__ U, int use_bn) {
    __shared__ __align__(16) float Xs[128][68];
    __shared__ __align__(16) float Us[4][64];
    __shared__ float cU[4];
    int tid = threadIdx.x;
    int nb = blockIdx.x * 128;
    const float* Xp = X ? X : g_H;

    // stage U with scale folded
    {
        int m = tid >> 6, k = tid & 63;
        float sck = use_bn ? g_scale[k] : 1.f;
        Us[m][k] = U[tid] * sck;
    }
    if (tid < 4) {
        float c = 0.f;
        if (use_bn) {
            for (int k = 0; k < 64; k++) c = fmaf(g_shift[k], U[tid * 64 + k], c);
        }
        cU[tid] = c;
    }
    // stage X tile coalesced (raw copy; 2048 float4s, 8 per thread)
    #pragma unroll
    for (int it = 0; it < 8; it++) {
        int idx4 = it * 256 + tid;
        int r = idx4 >> 4;
        int c4 = (idx4 & 15) << 2;
        int node = nb + r;
        float4 v = make_float4(0.f, 0.f, 0.f, 0.f);
        if (node < NN) v = *(const float4*)(Xp + (size_t)node * CH + c4);
        *(float4*)&Xs[r][c4] = v;
    }
    __syncthreads();

    // compute: thread -> (node r, head pair m0)
    int r = tid >> 1;
    int m0 = (tid & 1) * 2;
    float acc0 = cU[m0], acc1 = cU[m0 + 1];
    #pragma unroll
    for (int k = 0; k < 64; k += 4) {
        float4 xv = *(const float4*)&Xs[r][k];
        float4 u0 = *(const float4*)&Us[m0][k];
        float4 u1 = *(const float4*)&Us[m0 + 1][k];
        acc0 = fmaf(xv.x, u0.x, fmaf(xv.y, u0.y, fmaf(xv.z, u0.z, fmaf(xv.w, u0.w, acc0))));
        acc1 = fmaf(xv.x, u1.x, fmaf(xv.y, u1.y, fmaf(xv.z, u1.z, fmaf(xv.w, u1.w, acc1))));
    }
    int node = nb + r;
    if (node < NN) {
        *(float2*)(g_L + (size_t)node * 4 + m0) = make_float2(acc0, acc1);
    }
}

// ---------------- per-edge attention in CSR order (2 edges/thread) + fused W permute ----------------
__global__ void k_attn(const float* __restrict__ cc, const float* __restrict__ W) {
    int g = blockIdx.x * blockDim.x + threadIdx.x;
    if (blockIdx.x < 64) {
        int idx = blockIdx.x * 256 + threadIdx.x;   // 0..16383
        int r = idx >> 6;   // W row = m*64+o
        int c = idx & 63;   // channel
        int m = r >> 6;
        int o = r & 63;
        g_Wp[(c * 4 + m) * CH + o] = W[idx];
    }
    int p = 2 * g;
    if (p >= NE) return;
    int2 sp = *(const int2*)(g_srcP + p);
    int2 dp = *(const int2*)(g_dstP + p);
    float c0 = cc[0], c1 = cc[1], c2 = cc[2], c3 = cc[3];

    float4 ls0 = *(const float4*)(g_L + (size_t)sp.x * 4);
    float4 ld0 = *(const float4*)(g_L + (size_t)dp.x * 4);
    float4 ls1 = *(const float4*)(g_L + (size_t)sp.y * 4);
    float4 ld1 = *(const float4*)(g_L + (size_t)dp.y * 4);

    {
        float l0 = ld0.x - ls0.x + c0;
        float l1 = ld0.y - ls0.y + c1;
        float l2 = ld0.z - ls0.z + c2;
        float l3 = ld0.w - ls0.w + c3;
        float mx = fmaxf(fmaxf(l0, l1), fmaxf(l2, l3));
        float e0 = __expf(l0 - mx), e1 = __expf(l1 - mx), e2 = __expf(l2 - mx), e3 = __expf(l3 - mx);
        float inv = __fdividef(1.f, e0 + e1 + e2 + e3);
        *(float4*)(g_attnP + (size_t)p * 4) = make_float4(e0 * inv, e1 * inv, e2 * inv, e3 * inv);
    }
    {
        float l0 = ld1.x - ls1.x + c0;
        float l1 = ld1.y - ls1.y + c1;
        float l2 = ld1.z - ls1.z + c2;
        float l3 = ld1.w - ls1.w + c3;
        float mx = fmaxf(fmaxf(l0, l1), fmaxf(l2, l3));
        float e0 = __expf(l0 - mx), e1 = __expf(l1 - mx), e2 = __expf(l2 - mx), e3 = __expf(l3 - mx);
        float inv = __fdividef(1.f, e0 + e1 + e2 + e3);
        *(float4*)(g_attnP + (size_t)(p + 1) * 4) = make_float4(e0 * inv, e1 * inv, e2 * inv, e3 * inv);
    }
}

// ---------------- warp-per-node aggregation into Z (f32x2, depth-2 software pipeline) ----------------
__global__ void k_edge(const float* __restrict__ X, const float* __restrict__ cc, int use_bn) {
    int w = (blockIdx.x * blockDim.x + threadIdx.x) >> 5;
    int t = threadIdx.x & 31;
    if (w >= NN) return;
    const float* Xp = X ? X : g_H;
    int lo = g_rowptr[w] + g_boff[w >> 8];
    int hi = (w + 1 < NN) ? (g_rowptr[w + 1] + g_boff[(w + 1) >> 8]) : NE;
    float inv = __fdividef(1.f, (float)(hi - lo + 1));
    int k0 = 2 * t;
    float sc0 = 1.f, sc1 = 1.f, sh0 = 0.f, sh1 = 0.f;
    if (use_bn) { sc0 = g_scale[k0]; sc1 = g_scale[k0 + 1]; sh0 = g_shift[k0]; sh1 = g_shift[k0 + 1]; }

    // self-loop attention = softmax(c)
    float c0 = cc[0], c1 = cc[1], c2 = cc[2], c3 = cc[3];
    float mx = fmaxf(fmaxf(c0, c1), fmaxf(c2, c3));
    float e0 = __expf(c0 - mx), e1 = __expf(c1 - mx), e2 = __expf(c2 - mx), e3 = __expf(c3 - mx);
    float si = __fdividef(1.f, e0 + e1 + e2 + e3);
    ull W01 = pk2(e0 * si, e1 * si);
    ull W23 = pk2(e2 * si, e3 * si);

    float2 xv = *(const float2*)(Xp + (size_t)w * CH + k0);
    float xv0 = fmaf(xv.x, sc0, sh0);
    float xv1 = fmaf(xv.y, sc1, sh1);
    ull acc00 = mul2(pk2(xv0, xv0), W01);
    ull acc01 = mul2(pk2(xv0, xv0), W23);
    ull acc10 = mul2(pk2(xv1, xv1), W01);
    ull acc11 = mul2(pk2(xv1, xv1), W23);

    int i = lo;
    float2 x0, x1, x2, x3;
    if (i + 4 <= hi) {
        int s0 = g_srcP[i], s1 = g_srcP[i + 1], s2 = g_srcP[i + 2], s3 = g_srcP[i + 3];
        x0 = *(const float2*)(Xp + (size_t)s0 * CH + k0);
        x1 = *(const float2*)(Xp + (size_t)s1 * CH + k0);
        x2 = *(const float2*)(Xp + (size_t)s2 * CH + k0);
        x3 = *(const float2*)(Xp + (size_t)s3 * CH + k0);
    }
    for (; i + 4 <= hi; i += 4) {
        ulonglong2 A0 = *(const ulonglong2*)(g_attnP + (size_t)(i)     * 4);
        ulonglong2 A1 = *(const ulonglong2*)(g_attnP + (size_t)(i + 1) * 4);
        ulonglong2 A2 = *(const ulonglong2*)(g_attnP + (size_t)(i + 2) * 4);
        ulonglong2 A3 = *(const ulonglong2*)(g_attnP + (size_t)(i + 3) * 4);
        // depth-2 pipeline: issue next iteration's gathers before this iteration's FMAs
        float2 nx0 = x0, nx1 = x1, nx2 = x2, nx3 = x3;
        if (i + 8 <= hi) {
            int s0 = g_srcP[i + 4], s1 = g_srcP[i + 5], s2 = g_srcP[i + 6], s3 = g_srcP[i + 7];
            nx0 = *(const float2*)(Xp + (size_t)s0 * CH + k0);
            nx1 = *(const float2*)(Xp + (size_t)s1 * CH + k0);
            nx2 = *(const float2*)(Xp + (size_t)s2 * CH + k0);
            nx3 = *(const float2*)(Xp + (size_t)s3 * CH + k0);
        }

        float a0 = fmaf(x0.x, sc0, sh0), b0 = fmaf(x0.y, sc1, sh1);
        ull pa0 = pk2(a0, a0), pb0 = pk2(b0, b0);
        acc00 = fma2(pa0, A0.x, acc00); acc01 = fma2(pa0, A0.y, acc01);
        acc10 = fma2(pb0, A0.x, acc10); acc11 = fma2(pb0, A0.y, acc11);

        float a1 = fmaf(x1.x, sc0, sh0), b1 = fmaf(x1.y, sc1, sh1);
        ull pa1 = pk2(a1, a1), pb1 = pk2(b1, b1);
        acc00 = fma2(pa1, A1.x, acc00); acc01 = fma2(pa1, A1.y, acc01);
        acc10 = fma2(pb1, A1.x, acc10); acc11 = fma2(pb1, A1.y, acc11);

        float a2 = fmaf(x2.x, sc0, sh0), b2 = fmaf(x2.y, sc1, sh1);
        ull pa2 = pk2(a2, a2), pb2 = pk2(b2, b2);
        acc00 = fma2(pa2, A2.x, acc00); acc01 = fma2(pa2, A2.y, acc01);
        acc10 = fma2(pb2, A2.x, acc10); acc11 = fma2(pb2, A2.y, acc11);

        float a3 = fmaf(x3.x, sc0, sh0), b3 = fmaf(x3.y, sc1, sh1);
        ull pa3 = pk2(a3, a3), pb3 = pk2(b3, b3);
        acc00 = fma2(pa3, A3.x, acc00); acc01 = fma2(pa3, A3.y, acc01);
        acc10 = fma2(pb3, A3.x, acc10); acc11 = fma2(pb3, A3.y, acc11);

        x0 = nx0; x1 = nx1; x2 = nx2; x3 = nx3;
    }
    for (; i < hi; i++) {
        int s = g_srcP[i];
        ulonglong2 A = *(const ulonglong2*)(g_attnP + (size_t)i * 4);
        float2 x = *(const float2*)(Xp + (size_t)s * CH + k0);
        float a = fmaf(x.x, sc0, sh0), b = fmaf(x.y, sc1, sh1);
        ull pa = pk2(a, a), pb = pk2(b, b);
        acc00 = fma2(pa, A.x, acc00); acc01 = fma2(pa, A.y, acc01);
        acc10 = fma2(pb, A.x, acc10); acc11 = fma2(pb, A.y, acc11);
    }

    ull iv = pk2(inv, inv);
    ulonglong2 r0, r1;
    r0.x = mul2(acc00, iv); r0.y = mul2(acc01, iv);
    r1.x = mul2(acc10, iv); r1.y = mul2(acc11, iv);
    float* zr = g_Z + (size_t)w * KZ + k0 * 4;
    *(ulonglong2*)(zr)     = r0;
    *(ulonglong2*)(zr + 4) = r1;
}

// ---------------- dense GEMM (f32x2) + fence-free BN partial epilogue + deg re-zero ----------------
__global__ void __launch_bounds__(256) k_gemm(const float* __restrict__ b,
                                              float* __restrict__ extout, int relu,
                                              int do_bn, int zero_deg) {
    __shared__ __align__(16) float Xs[64 * 132];
    int tid = threadIdx.x;
    int nb = blockIdx.x * 128;
    float* out = extout ? extout : g_H;

    // re-zero g_deg for the next replay (runs after this replay's CSR build)
    if (zero_deg) {
        int i = blockIdx.x * 256 + tid;
        if (i < NN) g_deg[i] = 0;
    }

    ull acc[4][4];  // [node pair][col]
    #pragma unroll
    for (int p = 0; p < 4; p++)
        #pragma unroll
        for (int j = 0; j < 4; j++) acc[p][j] = 0ull;

    int tx = tid & 15;      // col group (4 cols)
    int ty = tid >> 4;      // node group (8 nodes)

    for (int kc = 0; kc < 4; kc++) {
        #pragma unroll
        for (int i = 0; i < 8; i++) {
            int f = i * 256 + tid;
            int nl = f >> 4;
            int kl = (f & 15) << 2;
            int node = nb + nl;
            float4 z = make_float4(0.f, 0.f, 0.f, 0.f);
            if (node < NN) z = *(const float4*)(g_Z + (size_t)node * KZ + kc * 64 + kl);
            Xs[(kl + 0) * 132 + nl] = z.x;
            Xs[(kl + 1) * 132 + nl] = z.y;
            Xs[(kl + 2) * 132 + nl] = z.z;
            Xs[(kl + 3) * 132 + nl] = z.w;
        }
        __syncthreads();
        #pragma unroll 8
        for (int kk = 0; kk < 64; kk++) {
            const float* xr = Xs + kk * 132 + ty * 8;
            ulonglong2 xa = *(const ulonglong2*)xr;
            ulonglong2 xb = *(const ulonglong2*)(xr + 4);
            float4 wv = *(const float4*)(g_Wp + (size_t)(kc * 64 + kk) * CH + tx * 4);
            ull w0 = pk2(wv.x, wv.x), w1 = pk2(wv.y, wv.y);
            ull w2 = pk2(wv.z, wv.z), w3 = pk2(wv.w, wv.w);
            acc[0][0] = fma2(xa.x, w0, acc[0][0]); acc[0][1] = fma2(xa.x, w1, acc[0][1]);
            acc[0][2] = fma2(xa.x, w2, acc[0][2]); acc[0][3] = fma2(xa.x, w3, acc[0][3]);
            acc[1][0] = fma2(xa.y, w0, acc[1][0]); acc[1][1] = fma2(xa.y, w1, acc[1][1]);
            acc[1][2] = fma2(xa.y, w2, acc[1][2]); acc[1][3] = fma2(xa.y, w3, acc[1][3]);
            acc[2][0] = fma2(xb.x, w0, acc[2][0]); acc[2][1] = fma2(xb.x, w1, acc[2][1]);
            acc[2][2] = fma2(xb.x, w2, acc[2][2]); acc[2][3] = fma2(xb.x, w3, acc[2][3]);
            acc[3][0] = fma2(xb.y, w0, acc[3][0]); acc[3][1] = fma2(xb.y, w1, acc[3][1]);
            acc[3][2] = fma2(xb.y, w2, acc[3][2]); acc[3][3] = fma2(xb.y, w3, acc[3][3]);
        }
        __syncthreads();
    }

    float4 bv = *(const float4*)(b + tx * 4);
    float s[4] = {0.f, 0.f, 0.f, 0.f};
    float q[4] = {0.f, 0.f, 0.f, 0.f};
    #pragma unroll
    for (int p = 0; p < 4; p++) {
        float lo0, hi0, lo1, hi1, lo2, hi2, lo3, hi3;
        upk2(lo0, hi0, acc[p][0]);
        upk2(lo1, hi1, acc[p][1]);
        upk2(lo2, hi2, acc[p][2]);
        upk2(lo3, hi3, acc[p][3]);
        int n0 = nb + ty * 8 + 2 * p;
        if (n0 < NN) {
            float4 r = make_float4(lo0 + bv.x, lo1 + bv.y, lo2 + bv.z, lo3 + bv.w);
            if (relu) {
                r.x = fmaxf(r.x, 0.f); r.y = fmaxf(r.y, 0.f);
                r.z = fmaxf(r.z, 0.f); r.w = fmaxf(r.w, 0.f);
            }
            *(float4*)(out + (size_t)n0 * CH + tx * 4) = r;
            s[0] += r.x; s[1] += r.y; s[2] += r.z; s[3] += r.w;
            q[0] = fmaf(r.x, r.x, q[0]); q[1] = fmaf(r.y, r.y, q[1]);
            q[2] = fmaf(r.z, r.z, q[2]); q[3] = fmaf(r.w, r.w, q[3]);
        }
        int n1 = n0 + 1;
        if (n1 < NN) {
            float4 r = make_float4(hi0 + bv.x, hi1 + bv.y, hi2 + bv.z, hi3 + bv.w);
            if (relu) {
                r.x = fmaxf(r.x, 0.f); r.y = fmaxf(r.y, 0.f);
                r.z = fmaxf(r.z, 0.f); r.w = fmaxf(r.w, 0.f);
            }
            *(float4*)(out + (size_t)n1 * CH + tx * 4) = r;
            s[0] += r.x; s[1] += r.y; s[2] += r.z; s[3] += r.w;
            q[0] = fmaf(r.x, r.x, q[0]); q[1] = fmaf(r.y, r.y, q[1]);
            q[2] = fmaf(r.z, r.z, q[2]); q[3] = fmaf(r.w, r.w, q[3]);
        }
    }

    if (!do_bn) return;
    // per-block BN partials from live registers — visible at kernel boundary, NO fence
    #pragma unroll
    for (int j = 0; j < 4; j++) {
        Xs[ty * 64 + tx * 4 + j]        = s[j];
        Xs[1024 + ty * 64 + tx * 4 + j] = q[j];
    }
    __syncthreads();
    if (tid < 64) {
        float S = 0.f, Q = 0.f;
        #pragma unroll
        for (int y = 0; y < 16; y++) {
            S += Xs[y * 64 + tid];
            Q += Xs[1024 + y * 64 + tid];
        }
        g_bnp[blockIdx.x * 64 + tid]  = S;
        g_bnp2[blockIdx.x * 64 + tid] = Q;
    }
}

// ---------------- BN final: reduce 235 block partials (4-way parallel) ----------------
__global__ void k_bnfinal(const float* __restrict__ g, const float* __restrict__ bt) {
    int ch = threadIdx.x & 63;
    int rg = threadIdx.x >> 6;   // 0..3
    float s = 0.f, s2 = 0.f;
    for (int blk = rg; blk < GEMM_BLOCKS; blk += 4) {
        s  += g_bnp[blk * 64 + ch];
        s2 += g_bnp2[blk * 64 + ch];
    }
    __shared__ float sh[4][64], sh2[4][64];
    sh[rg][ch] = s; sh2[rg][ch] = s2;
    __syncthreads();
    if (rg == 0) {
        s  = sh[0][ch]  + sh[1][ch]  + sh[2][ch]  + sh[3][ch];
        s2 = sh2[0][ch] + sh2[1][ch] + sh2[2][ch] + sh2[3][ch];
        float mu = s / (float)NN;
        float var = s2 / (float)NN - mu * mu;
        float sc = g[ch] * rsqrtf(var + 1e-5f);
        g_scale[ch] = sc;
        g_shift[ch] = bt[ch] - mu * sc;
    }
}

// ---------------- launch ----------------
extern "C" void kernel_launch(void* const* d_in, const int* in_sizes, int n_in,
                              void* d_out, int out_size) {
    const float* x    = (const float*)d_in[0];
    const int*   ei   = (const int*)d_in[1];      // edge_index: int32
    const float* W0   = (const float*)d_in[2];
    const float* U0   = (const float*)d_in[3];
    const float* c0   = (const float*)d_in[4];
    const float* b0   = (const float*)d_in[5];
    const float* g0   = (const float*)d_in[6];
    const float* bt0  = (const float*)d_in[7];
    const float* W1   = (const float*)d_in[8];
    const float* U1   = (const float*)d_in[9];
    const float* c1   = (const float*)d_in[10];
    const float* b1   = (const float*)d_in[11];
    const float* g1   = (const float*)d_in[12];
    const float* bt1  = (const float*)d_in[13];
    const float* W2   = (const float*)d_in[14];
    const float* U2   = (const float*)d_in[15];
    const float* c2   = (const float*)d_in[16];
    const float* b2   = (const float*)d_in[17];
    const int* srcE = ei;
    const int* dstE = ei + NE;
    float* out = (float*)d_out;

    const int GB_E  = (NE + 255) / 256;          // 1875
    const int GB_E2 = (NE / 2 + 255) / 256;      // 938 (2 edges/thread)
    const int GB_N  = SCAN_BLOCKS;               // 118
    const int GB_W  = NN / 8;                    // 3750 (warp per node, exact)
    const int GB_G  = GEMM_BLOCKS;               // 235
    const int GB_L  = (NN + 127) / 128;          // 235 (tiled k_L)

    // CSR build: 3 launches (deg pre-zeroed by module load / previous replay's gemm L0)
    k_count<<<GB_E2, 256>>>(dstE);
    k_scan<<<GB_N, 256>>>();
    k_scatter<<<GB_E, 256>>>(srcE, dstE);

    // ---- layer 0 ----
    k_L<<<GB_L, 256>>>(x, U0, 0);
    k_attn<<<GB_E2, 256>>>(c0, W0);
    k_edge<<<GB_W, 256>>>(x, c0, 0);
    k_gemm<<<GB_G, 256>>>(b0, nullptr, 1, 1, 1);   // +bn partials, +deg re-zero
    k_bnfinal<<<1, 256>>>(g0, bt0);

    // ---- layer 1 ----
    k_L<<<GB_L, 256>>>(nullptr, U1, 1);
    k_attn<<<GB_E2, 256>>>(c1, W1);
    k_edge<<<GB_W, 256>>>(nullptr, c1, 1);
    k_gemm<<<GB_G, 256>>>(b1, nullptr, 1, 1, 0);
    k_bnfinal<<<1, 256>>>(g1, bt1);

    // ---- layer 2 ----
    k_L<<<GB_L, 256>>>(nullptr, U2, 1);
    k_attn<<<GB_E2, 256>>>(c2, W2);
    k_edge<<<GB_W, 256>>>(nullptr, c2, 1);
    k_gemm<<<GB_G, 256>>>(b2, out, 0, 0, 0);

    (void)in_sizes; (void)n_in; (void)out_size;
}

// round 14
// speedup vs baseline: 1.0018x; 1.0018x over previous
#include <cuda_runtime.h>

#define NN 30000
#define NE 480000
#define CH 64
#define NHEADS 4
#define KZ 256          // 64 channels x 4 heads
#define SCAN_BLOCKS ((NN + 255) / 256)   // 118
#define GEMM_BLOCKS ((NN + 127) / 128)   // 235

typedef unsigned long long ull;

// ---------------- f32x2 helpers (sm_103a packed fp32 pipe) ----------------
__device__ __forceinline__ ull pk2(float lo, float hi) {
    ull r;
    asm("mov.b64 %0, {%1, %2};" : "=l"(r) : "f"(lo), "f"(hi));
    return r;
}
__device__ __forceinline__ void upk2(float& lo, float& hi, ull v) {
    asm("mov.b64 {%0, %1}, %2;" : "=f"(lo), "=f"(hi) : "l"(v));
}
__device__ __forceinline__ ull fma2(ull a, ull b, ull c) {
    ull d;
    asm("fma.rn.f32x2 %0, %1, %2, %3;" : "=l"(d) : "l"(a), "l"(b), "l"(c));
    return d;
}
__device__ __forceinline__ ull mul2(ull a, ull b) {
    ull d;
    asm("mul.rn.f32x2 %0, %1, %2;" : "=l"(d) : "l"(a), "l"(b));
    return d;
}

// ---------------- scratch (device globals; no allocations allowed) ----------------
__device__ __align__(16) float g_L[NN * 4];        // per-node head logits
__device__ __align__(16) float g_attnP[NE * 4];    // per-edge attention, CSR order
__device__ __align__(16) float g_Z[NN * KZ];       // aggregated weighted features [node][c*4+m]
__device__ __align__(16) float g_H[NN * CH];       // relu(conv) output between layers
__device__ __align__(16) float g_Wp[KZ * CH];      // permuted weight for current layer
__device__ int   g_deg[NN];                        // zeroed at module load; re-zeroed by k_gemm L0
__device__ int   g_rowptr[NN];                     // block-local exclusive prefix
__device__ int   g_wptr[NN];                       // block-local write cursor
__device__ int   g_srcP[NE];                       // src node per CSR position
__device__ int   g_dstP[NE];                       // dst node per CSR position
__device__ int   g_bsum[SCAN_BLOCKS];
__device__ int   g_boff[SCAN_BLOCKS];              // per-256-node-block global offset
__device__ int   g_ctr;                            // scan completion counter (self-resetting)
__device__ float g_bnp[GEMM_BLOCKS * CH];
__device__ float g_bnp2[GEMM_BLOCKS * CH];
__device__ float g_scale[CH];
__device__ float g_shift[CH];

// ---------------- CSR build ----------------
__global__ void k_count(const int* __restrict__ dstE) {
    int g = blockIdx.x * blockDim.x + threadIdx.x;
    int e = 2 * g;
    if (e < NE) {
        int2 d = *(const int2*)(dstE + e);
        atomicAdd(&g_deg[d.x], 1);
        atomicAdd(&g_deg[d.y], 1);
    }
}

// fused scan: per-block local scan; last block scans the 118 block sums.
__global__ void k_scan() {
    int b = blockIdx.x, t = threadIdx.x;
    int i = b * 256 + t;
    int v = (i < NN) ? g_deg[i] : 0;
    int lane = t & 31, wid = t >> 5;
    int x = v;
    #pragma unroll
    for (int off = 1; off < 32; off <<= 1) {
        int y = __shfl_up_sync(0xFFFFFFFFu, x, off);
        if (lane >= off) x += y;
    }
    __shared__ int wsum[8];
    __shared__ int sIsLast;
    if (lane == 31) wsum[wid] = x;
    __syncthreads();
    if (wid == 0) {
        int s = (lane < 8) ? wsum[lane] : 0;
        #pragma unroll
        for (int off = 1; off < 8; off <<= 1) {
            int y = __shfl_up_sync(0xFFFFFFFFu, s, off);
            if (lane >= off) s += y;
        }
        if (lane < 8) wsum[lane] = s;   // inclusive warp sums
    }
    __syncthreads();
    int base = (wid > 0) ? wsum[wid - 1] : 0;
    int excl = base + x - v;
    if (i < NN) { g_rowptr[i] = excl; g_wptr[i] = excl; }
    if (t == 255) g_bsum[b] = base + x;

    // last block scans the block sums into g_boff
    __threadfence();   // tiny kernel: L1 flush harmless here
    __syncthreads();
    if (t == 0) sIsLast = (atomicAdd(&g_ctr, 1) == (int)gridDim.x - 1);
    __syncthreads();
    if (sIsLast) {
        int v2 = (t < SCAN_BLOCKS) ? g_bsum[t] : 0;
        int x2 = v2;
        #pragma unroll
        for (int off = 1; off < 32; off <<= 1) {
            int y = __shfl_up_sync(0xFFFFFFFFu, x2, off);
            if (lane >= off) x2 += y;
        }
        __shared__ int ws2[8];
        if (lane == 31) ws2[wid] = x2;
        __syncthreads();
        if (t == 0) {
            int a = 0;
            #pragma unroll
            for (int wv = 0; wv < 8; wv++) { int tmp = ws2[wv]; ws2[wv] = a; a += tmp; }
            g_ctr = 0;   // self-reset for next replay
        }
        __syncthreads();
        if (t < SCAN_BLOCKS) g_boff[t] = ws2[wid] + x2 - v2;
    }
}

__global__ void k_scatter(const int* __restrict__ srcE, const int* __restrict__ dstE) {
    int e = blockIdx.x * blockDim.x + threadIdx.x;
    if (e < NE) {
        int s = srcE[e];
        int d = dstE[e];
        int p = atomicAdd(&g_wptr[d], 1) + g_boff[d >> 8];
        g_srcP[p] = s;
        g_dstP[p] = d;
    }
}

// ---------------- per-node head logits (tiled): L[n][m] = xhat[n]@U[m] ----------------
// 128 nodes/block, BN folded into U' = U*sc and constant cU[m] = sum_k sh[k]*U[m][k].
__global__ void __launch_bounds__(256) k_L(const float* __restrict__ X,
                                           const float* __restrict__ U, int use_bn) {
    __shared__ __align__(16) float Xs[128][68];
    __shared__ __align__(16) float Us[4][64];
    __shared__ float cU[4];
    int tid = threadIdx.x;
    int nb = blockIdx.x * 128;
    const float* Xp = X ? X : g_H;

    // stage U with scale folded
    {
        int m = tid >> 6, k = tid & 63;
        float sck = use_bn ? g_scale[k] : 1.f;
        Us[m][k] = U[tid] * sck;
    }
    if (tid < 4) {
        float c = 0.f;
        if (use_bn) {
            for (int k = 0; k < 64; k++) c = fmaf(g_shift[k], U[tid * 64 + k], c);
        }
        cU[tid] = c;
    }
    // stage X tile coalesced (raw copy; 2048 float4s, 8 per thread)
    #pragma unroll
    for (int it = 0; it < 8; it++) {
        int idx4 = it * 256 + tid;
        int r = idx4 >> 4;
        int c4 = (idx4 & 15) << 2;
        int node = nb + r;
        float4 v = make_float4(0.f, 0.f, 0.f, 0.f);
        if (node < NN) v = *(const float4*)(Xp + (size_t)node * CH + c4);
        *(float4*)&Xs[r][c4] = v;
    }
    __syncthreads();

    // compute: thread -> (node r, head pair m0)
    int r = tid >> 1;
    int m0 = (tid & 1) * 2;
    float acc0 = cU[m0], acc1 = cU[m0 + 1];
    #pragma unroll
    for (int k = 0; k < 64; k += 4) {
        float4 xv = *(const float4*)&Xs[r][k];
        float4 u0 = *(const float4*)&Us[m0][k];
        float4 u1 = *(const float4*)&Us[m0 + 1][k];
        acc0 = fmaf(xv.x, u0.x, fmaf(xv.y, u0.y, fmaf(xv.z, u0.z, fmaf(xv.w, u0.w, acc0))));
        acc1 = fmaf(xv.x, u1.x, fmaf(xv.y, u1.y, fmaf(xv.z, u1.z, fmaf(xv.w, u1.w, acc1))));
    }
    int node = nb + r;
    if (node < NN) {
        *(float2*)(g_L + (size_t)node * 4 + m0) = make_float2(acc0, acc1);
    }
}

// ---------------- per-edge attention in CSR order (2 edges/thread) + fused W permute ----------------
__global__ void k_attn(const float* __restrict__ cc, const float* __restrict__ W) {
    int g = blockIdx.x * blockDim.x + threadIdx.x;
    if (blockIdx.x < 64) {
        int idx = blockIdx.x * 256 + threadIdx.x;   // 0..16383
        int r = idx >> 6;   // W row = m*64+o
        int c = idx & 63;   // channel
        int m = r >> 6;
        int o = r & 63;
        g_Wp[(c * 4 + m) * CH + o] = W[idx];
    }
    int p = 2 * g;
    if (p >= NE) return;
    int2 sp = *(const int2*)(g_srcP + p);
    int2 dp = *(const int2*)(g_dstP + p);
    float c0 = cc[0], c1 = cc[1], c2 = cc[2], c3 = cc[3];

    float4 ls0 = *(const float4*)(g_L + (size_t)sp.x * 4);
    float4 ld0 = *(const float4*)(g_L + (size_t)dp.x * 4);
    float4 ls1 = *(const float4*)(g_L + (size_t)sp.y * 4);
    float4 ld1 = *(const float4*)(g_L + (size_t)dp.y * 4);

    {
        float l0 = ld0.x - ls0.x + c0;
        float l1 = ld0.y - ls0.y + c1;
        float l2 = ld0.z - ls0.z + c2;
        float l3 = ld0.w - ls0.w + c3;
        float mx = fmaxf(fmaxf(l0, l1), fmaxf(l2, l3));
        float e0 = __expf(l0 - mx), e1 = __expf(l1 - mx), e2 = __expf(l2 - mx), e3 = __expf(l3 - mx);
        float inv = __fdividef(1.f, e0 + e1 + e2 + e3);
        *(float4*)(g_attnP + (size_t)p * 4) = make_float4(e0 * inv, e1 * inv, e2 * inv, e3 * inv);
    }
    {
        float l0 = ld1.x - ls1.x + c0;
        float l1 = ld1.y - ls1.y + c1;
        float l2 = ld1.z - ls1.z + c2;
        float l3 = ld1.w - ls1.w + c3;
        float mx = fmaxf(fmaxf(l0, l1), fmaxf(l2, l3));
        float e0 = __expf(l0 - mx), e1 = __expf(l1 - mx), e2 = __expf(l2 - mx), e3 = __expf(l3 - mx);
        float inv = __fdividef(1.f, e0 + e1 + e2 + e3);
        *(float4*)(g_attnP + (size_t)(p + 1) * 4) = make_float4(e0 * inv, e1 * inv, e2 * inv, e3 * inv);
    }
}

// ---------------- warp-per-node aggregation into Z (f32x2, depth-2 software pipeline) ----------------
__global__ void k_edge(const float* __restrict__ X, const float* __restrict__ cc, int use_bn) {
    int w = (blockIdx.x * blockDim.x + threadIdx.x) >> 5;
    int t = threadIdx.x & 31;
    if (w >= NN) return;
    const float* Xp = X ? X : g_H;
    int lo = g_rowptr[w] + g_boff[w >> 8];
    int hi = (w + 1 < NN) ? (g_rowptr[w + 1] + g_boff[(w + 1) >> 8]) : NE;
    float inv = __fdividef(1.f, (float)(hi - lo + 1));
    int k0 = 2 * t;
    float sc0 = 1.f, sc1 = 1.f, sh0 = 0.f, sh1 = 0.f;
    if (use_bn) { sc0 = g_scale[k0]; sc1 = g_scale[k0 + 1]; sh0 = g_shift[k0]; sh1 = g_shift[k0 + 1]; }

    // self-loop attention = softmax(c)
    float c0 = cc[0], c1 = cc[1], c2 = cc[2], c3 = cc[3];
    float mx = fmaxf(fmaxf(c0, c1), fmaxf(c2, c3));
    float e0 = __expf(c0 - mx), e1 = __expf(c1 - mx), e2 = __expf(c2 - mx), e3 = __expf(c3 - mx);
    float si = __fdividef(1.f, e0 + e1 + e2 + e3);
    ull W01 = pk2(e0 * si, e1 * si);
    ull W23 = pk2(e2 * si, e3 * si);

    float2 xv = *(const float2*)(Xp + (size_t)w * CH + k0);
    float xv0 = fmaf(xv.x, sc0, sh0);
    float xv1 = fmaf(xv.y, sc1, sh1);
    ull acc00 = mul2(pk2(xv0, xv0), W01);
    ull acc01 = mul2(pk2(xv0, xv0), W23);
    ull acc10 = mul2(pk2(xv1, xv1), W01);
    ull acc11 = mul2(pk2(xv1, xv1), W23);

    int i = lo;
    float2 x0, x1, x2, x3;
    if (i + 4 <= hi) {
        int s0 = g_srcP[i], s1 = g_srcP[i + 1], s2 = g_srcP[i + 2], s3 = g_srcP[i + 3];
        x0 = *(const float2*)(Xp + (size_t)s0 * CH + k0);
        x1 = *(const float2*)(Xp + (size_t)s1 * CH + k0);
        x2 = *(const float2*)(Xp + (size_t)s2 * CH + k0);
        x3 = *(const float2*)(Xp + (size_t)s3 * CH + k0);
    }
    for (; i + 4 <= hi; i += 4) {
        ulonglong2 A0 = *(const ulonglong2*)(g_attnP + (size_t)(i)     * 4);
        ulonglong2 A1 = *(const ulonglong2*)(g_attnP + (size_t)(i + 1) * 4);
        ulonglong2 A2 = *(const ulonglong2*)(g_attnP + (size_t)(i + 2) * 4);
        ulonglong2 A3 = *(const ulonglong2*)(g_attnP + (size_t)(i + 3) * 4);
        // depth-2 pipeline: issue next iteration's gathers before this iteration's FMAs
        float2 nx0 = x0, nx1 = x1, nx2 = x2, nx3 = x3;
        if (i + 8 <= hi) {
            int s0 = g_srcP[i + 4], s1 = g_srcP[i + 5], s2 = g_srcP[i + 6], s3 = g_srcP[i + 7];
            nx0 = *(const float2*)(Xp + (size_t)s0 * CH + k0);
            nx1 = *(const float2*)(Xp + (size_t)s1 * CH + k0);
            nx2 = *(const float2*)(Xp + (size_t)s2 * CH + k0);
            nx3 = *(const float2*)(Xp + (size_t)s3 * CH + k0);
        }

        float a0 = fmaf(x0.x, sc0, sh0), b0 = fmaf(x0.y, sc1, sh1);
        ull pa0 = pk2(a0, a0), pb0 = pk2(b0, b0);
        acc00 = fma2(pa0, A0.x, acc00); acc01 = fma2(pa0, A0.y, acc01);
        acc10 = fma2(pb0, A0.x, acc10); acc11 = fma2(pb0, A0.y, acc11);

        float a1 = fmaf(x1.x, sc0, sh0), b1 = fmaf(x1.y, sc1, sh1);
        ull pa1 = pk2(a1, a1), pb1 = pk2(b1, b1);
        acc00 = fma2(pa1, A1.x, acc00); acc01 = fma2(pa1, A1.y, acc01);
        acc10 = fma2(pb1, A1.x, acc10); acc11 = fma2(pb1, A1.y, acc11);

        float a2 = fmaf(x2.x, sc0, sh0), b2 = fmaf(x2.y, sc1, sh1);
        ull pa2 = pk2(a2, a2), pb2 = pk2(b2, b2);
        acc00 = fma2(pa2, A2.x, acc00); acc01 = fma2(pa2, A2.y, acc01);
        acc10 = fma2(pb2, A2.x, acc10); acc11 = fma2(pb2, A2.y, acc11);

        float a3 = fmaf(x3.x, sc0, sh0), b3 = fmaf(x3.y, sc1, sh1);
        ull pa3 = pk2(a3, a3), pb3 = pk2(b3, b3);
        acc00 = fma2(pa3, A3.x, acc00); acc01 = fma2(pa3, A3.y, acc01);
        acc10 = fma2(pb3, A3.x, acc10); acc11 = fma2(pb3, A3.y, acc11);

        x0 = nx0; x1 = nx1; x2 = nx2; x3 = nx3;
    }
    for (; i < hi; i++) {
        int s = g_srcP[i];
        ulonglong2 A = *(const ulonglong2*)(g_attnP + (size_t)i * 4);
        float2 x = *(const float2*)(Xp + (size_t)s * CH + k0);
        float a = fmaf(x.x, sc0, sh0), b = fmaf(x.y, sc1, sh1);
        ull pa = pk2(a, a), pb = pk2(b, b);
        acc00 = fma2(pa, A.x, acc00); acc01 = fma2(pa, A.y, acc01);
        acc10 = fma2(pb, A.x, acc10); acc11 = fma2(pb, A.y, acc11);
    }

    ull iv = pk2(inv, inv);
    ulonglong2 r0, r1;
    r0.x = mul2(acc00, iv); r0.y = mul2(acc01, iv);
    r1.x = mul2(acc10, iv); r1.y = mul2(acc11, iv);
    float* zr = g_Z + (size_t)w * KZ + k0 * 4;
    *(ulonglong2*)(zr)     = r0;
    *(ulonglong2*)(zr + 4) = r1;
}

// ---------------- dense GEMM (f32x2) + fence-free BN partial epilogue + deg re-zero ----------------
__global__ void __launch_bounds__(256) k_gemm(const float* __restrict__ b,
                                              float* __restrict__ extout, int relu,
                                              int do_bn, int zero_deg) {
    __shared__ __align__(16) float Xs[64 * 132];
    int tid = threadIdx.x;
    int nb = blockIdx.x * 128;
    float* out = extout ? extout : g_H;

    // re-zero g_deg for the next replay (runs after this replay's CSR build)
    if (zero_deg) {
        int i = blockIdx.x * 256 + tid;
        if (i < NN) g_deg[i] = 0;
    }

    ull acc[4][4];  // [node pair][col]
    #pragma unroll
    for (int p = 0; p < 4; p++)
        #pragma unroll
        for (int j = 0; j < 4; j++) acc[p][j] = 0ull;

    int tx = tid & 15;      // col group (4 cols)
    int ty = tid >> 4;      // node group (8 nodes)

    for (int kc = 0; kc < 4; kc++) {
        #pragma unroll
        for (int i = 0; i < 8; i++) {
            int f = i * 256 + tid;
            int nl = f >> 4;
            int kl = (f & 15) << 2;
            int node = nb + nl;
            float4 z = make_float4(0.f, 0.f, 0.f, 0.f);
            if (node < NN) z = *(const float4*)(g_Z + (size_t)node * KZ + kc * 64 + kl);
            Xs[(kl + 0) * 132 + nl] = z.x;
            Xs[(kl + 1) * 132 + nl] = z.y;
            Xs[(kl + 2) * 132 + nl] = z.z;
            Xs[(kl + 3) * 132 + nl] = z.w;
        }
        __syncthreads();
        #pragma unroll 8
        for (int kk = 0; kk < 64; kk++) {
            const float* xr = Xs + kk * 132 + ty * 8;
            ulonglong2 xa = *(const ulonglong2*)xr;
            ulonglong2 xb = *(const ulonglong2*)(xr + 4);
            float4 wv = *(const float4*)(g_Wp + (size_t)(kc * 64 + kk) * CH + tx * 4);
            ull w0 = pk2(wv.x, wv.x), w1 = pk2(wv.y, wv.y);
            ull w2 = pk2(wv.z, wv.z), w3 = pk2(wv.w, wv.w);
            acc[0][0] = fma2(xa.x, w0, acc[0][0]); acc[0][1] = fma2(xa.x, w1, acc[0][1]);
            acc[0][2] = fma2(xa.x, w2, acc[0][2]); acc[0][3] = fma2(xa.x, w3, acc[0][3]);
            acc[1][0] = fma2(xa.y, w0, acc[1][0]); acc[1][1] = fma2(xa.y, w1, acc[1][1]);
            acc[1][2] = fma2(xa.y, w2, acc[1][2]); acc[1][3] = fma2(xa.y, w3, acc[1][3]);
            acc[2][0] = fma2(xb.x, w0, acc[2][0]); acc[2][1] = fma2(xb.x, w1, acc[2][1]);
            acc[2][2] = fma2(xb.x, w2, acc[2][2]); acc[2][3] = fma2(xb.x, w3, acc[2][3]);
            acc[3][0] = fma2(xb.y, w0, acc[3][0]); acc[3][1] = fma2(xb.y, w1, acc[3][1]);
            acc[3][2] = fma2(xb.y, w2, acc[3][2]); acc[3][3] = fma2(xb.y, w3, acc[3][3]);
        }
        __syncthreads();
    }

    float4 bv = *(const float4*)(b + tx * 4);
    float s[4] = {0.f, 0.f, 0.f, 0.f};
    float q[4] = {0.f, 0.f, 0.f, 0.f};
    #pragma unroll
    for (int p = 0; p < 4; p++) {
        float lo0, hi0, lo1, hi1, lo2, hi2, lo3, hi3;
        upk2(lo0, hi0, acc[p][0]);
        upk2(lo1, hi1, acc[p][1]);
        upk2(lo2, hi2, acc[p][2]);
        upk2(lo3, hi3, acc[p][3]);
        int n0 = nb + ty * 8 + 2 * p;
        if (n0 < NN) {
            float4 r = make_float4(lo0 + bv.x, lo1 + bv.y, lo2 + bv.z, lo3 + bv.w);
            if (relu) {
                r.x = fmaxf(r.x, 0.f); r.y = fmaxf(r.y, 0.f);
                r.z = fmaxf(r.z, 0.f); r.w = fmaxf(r.w, 0.f);
            }
            *(float4*)(out + (size_t)n0 * CH + tx * 4) = r;
            s[0] += r.x; s[1] += r.y; s[2] += r.z; s[3] += r.w;
            q[0] = fmaf(r.x, r.x, q[0]); q[1] = fmaf(r.y, r.y, q[1]);
            q[2] = fmaf(r.z, r.z, q[2]); q[3] = fmaf(r.w, r.w, q[3]);
        }
        int n1 = n0 + 1;
        if (n1 < NN) {
            float4 r = make_float4(hi0 + bv.x, hi1 + bv.y, hi2 + bv.z, hi3 + bv.w);
            if (relu) {
                r.x = fmaxf(r.x, 0.f); r.y = fmaxf(r.y, 0.f);
                r.z = fmaxf(r.z, 0.f); r.w = fmaxf(r.w, 0.f);
            }
            *(float4*)(out + (size_t)n1 * CH + tx * 4) = r;
            s[0] += r.x; s[1] += r.y; s[2] += r.z; s[3] += r.w;
            q[0] = fmaf(r.x, r.x, q[0]); q[1] = fmaf(r.y, r.y, q[1]);
            q[2] = fmaf(r.z, r.z, q[2]); q[3] = fmaf(r.w, r.w, q[3]);
        }
    }

    if (!do_bn) return;
    // per-block BN partials from live registers — visible at kernel boundary, NO fence
    #pragma unroll
    for (int j = 0; j < 4; j++) {
        Xs[ty * 64 + tx * 4 + j]        = s[j];
        Xs[1024 + ty * 64 + tx * 4 + j] = q[j];
    }
    __syncthreads();
    if (tid < 64) {
        float S = 0.f, Q = 0.f;
        #pragma unroll
        for (int y = 0; y < 16; y++) {
            S += Xs[y * 64 + tid];
            Q += Xs[1024 + y * 64 + tid];
        }
        g_bnp[blockIdx.x * 64 + tid]  = S;
        g_bnp2[blockIdx.x * 64 + tid] = Q;
    }
}

// ---------------- BN final: reduce 235 block partials (4-way parallel) ----------------
__global__ void k_bnfinal(const float* __restrict__ g, const float* __restrict__ bt) {
    int ch = threadIdx.x & 63;
    int rg = threadIdx.x >> 6;   // 0..3
    float s = 0.f, s2 = 0.f;
    for (int blk = rg; blk < GEMM_BLOCKS; blk += 4) {
        s  += g_bnp[blk * 64 + ch];
        s2 += g_bnp2[blk * 64 + ch];
    }
    __shared__ float sh[4][64], sh2[4][64];
    sh[rg][ch] = s; sh2[rg][ch] = s2;
    __syncthreads();
    if (rg == 0) {
        s  = sh[0][ch]  + sh[1][ch]  + sh[2][ch]  + sh[3][ch];
        s2 = sh2[0][ch] + sh2[1][ch] + sh2[2][ch] + sh2[3][ch];
        float mu = s / (float)NN;
        float var = s2 / (float)NN - mu * mu;
        float sc = g[ch] * rsqrtf(var + 1e-5f);
        g_scale[ch] = sc;
        g_shift[ch] = bt[ch] - mu * sc;
    }
}

// ---------------- launch ----------------
extern "C" void kernel_launch(void* const* d_in, const int* in_sizes, int n_in,
                              void* d_out, int out_size) {
    const float* x    = (const float*)d_in[0];
    const int*   ei   = (const int*)d_in[1];      // edge_index: int32
    const float* W0   = (const float*)d_in[2];
    const float* U0   = (const float*)d_in[3];
    const float* c0   = (const float*)d_in[4];
    const float* b0   = (const float*)d_in[5];
    const float* g0   = (const float*)d_in[6];
    const float* bt0  = (const float*)d_in[7];
    const float* W1   = (const float*)d_in[8];
    const float* U1   = (const float*)d_in[9];
    const float* c1   = (const float*)d_in[10];
    const float* b1   = (const float*)d_in[11];
    const float* g1   = (const float*)d_in[12];
    const float* bt1  = (const float*)d_in[13];
    const float* W2   = (const float*)d_in[14];
    const float* U2   = (const float*)d_in[15];
    const float* c2   = (const float*)d_in[16];
    const float* b2   = (const float*)d_in[17];
    const int* srcE = ei;
    const int* dstE = ei + NE;
    float* out = (float*)d_out;

    const int GB_E  = (NE + 255) / 256;          // 1875
    const int GB_E2 = (NE / 2 + 255) / 256;      // 938 (2 edges/thread)
    const int GB_N  = SCAN_BLOCKS;               // 118
    const int GB_W  = NN / 8;                    // 3750 (warp per node, exact)
    const int GB_G  = GEMM_BLOCKS;               // 235
    const int GB_L  = (NN + 127) / 128;          // 235 (tiled k_L)

    // CSR build: 3 launches (deg pre-zeroed by module load / previous replay's gemm L0)
    k_count<<<GB_E2, 256>>>(dstE);
    k_scan<<<GB_N, 256>>>();
    k_scatter<<<GB_E, 256>>>(srcE, dstE);

    // ---- layer 0 ----
    k_L<<<GB_L, 256>>>(x, U0, 0);
    k_attn<<<GB_E2, 256>>>(c0, W0);
    k_edge<<<GB_W, 256>>>(x, c0, 0);
    k_gemm<<<GB_G, 256>>>(b0, nullptr, 1, 1, 1);   // +bn partials, +deg re-zero
    k_bnfinal<<<1, 256>>>(g0, bt0);

    // ---- layer 1 ----
    k_L<<<GB_L, 256>>>(nullptr, U1, 1);
    k_attn<<<GB_E2, 256>>>(c1, W1);
    k_edge<<<GB_W, 256>>>(nullptr, c1, 1);
    k_gemm<<<GB_G, 256>>>(b1, nullptr, 1, 1, 0);
    k_bnfinal<<<1, 256>>>(g1, bt1);

    // ---- layer 2 ----
    k_L<<<GB_L, 256>>>(nullptr, U2, 1);
    k_attn<<<GB_E2, 256>>>(c2, W2);
    k_edge<<<GB_W, 256>>>(nullptr, c2, 1);
    k_gemm<<<GB_G, 256>>>(b2, out, 0, 0, 0);

    (void)in_sizes; (void)n_in; (void)out_size;
}

// round 15
// speedup vs baseline: 1.0019x; 1.0001x over previous
#include <cuda_runtime.h>

#define NN 30000
#define NE 480000
#define CH 64
#define NHEADS 4
#define KZ 256          // 64 channels x 4 heads
#define SCAN_BLOCKS ((NN + 255) / 256)   // 118
#define GEMM_BLOCKS ((NN + 127) / 128)   // 235

typedef unsigned long long ull;

// ---------------- f32x2 helpers (sm_103a packed fp32 pipe) ----------------
__device__ __forceinline__ ull pk2(float lo, float hi) {
    ull r;
    asm("mov.b64 %0, {%1, %2};" : "=l"(r) : "f"(lo), "f"(hi));
    return r;
}
__device__ __forceinline__ void upk2(float& lo, float& hi, ull v) {
    asm("mov.b64 {%0, %1}, %2;" : "=f"(lo), "=f"(hi) : "l"(v));
}
__device__ __forceinline__ ull fma2(ull a, ull b, ull c) {
    ull d;
    asm("fma.rn.f32x2 %0, %1, %2, %3;" : "=l"(d) : "l"(a), "l"(b), "l"(c));
    return d;
}
__device__ __forceinline__ ull mul2(ull a, ull b) {
    ull d;
    asm("mul.rn.f32x2 %0, %1, %2;" : "=l"(d) : "l"(a), "l"(b));
    return d;
}

// ---------------- scratch (device globals; no allocations allowed) ----------------
__device__ __align__(16) float g_L[NN * 4];        // per-node head logits
__device__ __align__(16) float g_attnP[NE * 4];    // per-edge attention, CSR order
__device__ __align__(16) float g_Z[NN * KZ];       // aggregated weighted features [node][c*4+m]
__device__ __align__(16) float g_H[NN * CH];       // relu(conv) output between layers
__device__ __align__(16) float g_Wp[KZ * CH];      // permuted weight for current layer
__device__ int   g_deg[NN];                        // zeroed at module load; re-zeroed by k_gemm L0
__device__ int   g_rowptr[NN];                     // block-local exclusive prefix
__device__ int   g_wptr[NN];                       // block-local write cursor
__device__ int   g_srcP[NE];                       // src node per CSR position
__device__ int   g_dstP[NE];                       // dst node per CSR position
__device__ int   g_bsum[SCAN_BLOCKS];
__device__ int   g_boff[SCAN_BLOCKS];              // per-256-node-block global offset
__device__ int   g_ctr;                            // scan completion counter (self-resetting)
__device__ float g_bnp[GEMM_BLOCKS * CH];
__device__ float g_bnp2[GEMM_BLOCKS * CH];
__device__ float g_scale[CH];
__device__ float g_shift[CH];

// ---------------- CSR build ----------------
__global__ void k_count(const int* __restrict__ dstE) {
    int g = blockIdx.x * blockDim.x + threadIdx.x;
    int e = 2 * g;
    if (e < NE) {
        int2 d = *(const int2*)(dstE + e);
        atomicAdd(&g_deg[d.x], 1);
        atomicAdd(&g_deg[d.y], 1);
    }
}

// fused scan: per-block local scan; last block scans the 118 block sums.
__global__ void k_scan() {
    int b = blockIdx.x, t = threadIdx.x;
    int i = b * 256 + t;
    int v = (i < NN) ? g_deg[i] : 0;
    int lane = t & 31, wid = t >> 5;
    int x = v;
    #pragma unroll
    for (int off = 1; off < 32; off <<= 1) {
        int y = __shfl_up_sync(0xFFFFFFFFu, x, off);
        if (lane >= off) x += y;
    }
    __shared__ int wsum[8];
    __shared__ int sIsLast;
    if (lane == 31) wsum[wid] = x;
    __syncthreads();
    if (wid == 0) {
        int s = (lane < 8) ? wsum[lane] : 0;
        #pragma unroll
        for (int off = 1; off < 8; off <<= 1) {
            int y = __shfl_up_sync(0xFFFFFFFFu, s, off);
            if (lane >= off) s += y;
        }
        if (lane < 8) wsum[lane] = s;   // inclusive warp sums
    }
    __syncthreads();
    int base = (wid > 0) ? wsum[wid - 1] : 0;
    int excl = base + x - v;
    if (i < NN) { g_rowptr[i] = excl; g_wptr[i] = excl; }
    if (t == 255) g_bsum[b] = base + x;

    // last block scans the block sums into g_boff
    __threadfence();   // tiny kernel: L1 flush harmless here
    __syncthreads();
    if (t == 0) sIsLast = (atomicAdd(&g_ctr, 1) == (int)gridDim.x - 1);
    __syncthreads();
    if (sIsLast) {
        int v2 = (t < SCAN_BLOCKS) ? g_bsum[t] : 0;
        int x2 = v2;
        #pragma unroll
        for (int off = 1; off < 32; off <<= 1) {
            int y = __shfl_up_sync(0xFFFFFFFFu, x2, off);
            if (lane >= off) x2 += y;
        }
        __shared__ int ws2[8];
        if (lane == 31) ws2[wid] = x2;
        __syncthreads();
        if (t == 0) {
            int a = 0;
            #pragma unroll
            for (int wv = 0; wv < 8; wv++) { int tmp = ws2[wv]; ws2[wv] = a; a += tmp; }
            g_ctr = 0;   // self-reset for next replay
        }
        __syncthreads();
        if (t < SCAN_BLOCKS) g_boff[t] = ws2[wid] + x2 - v2;
    }
}

__global__ void k_scatter(const int* __restrict__ srcE, const int* __restrict__ dstE) {
    int e = blockIdx.x * blockDim.x + threadIdx.x;
    if (e < NE) {
        int s = srcE[e];
        int d = dstE[e];
        int p = atomicAdd(&g_wptr[d], 1) + g_boff[d >> 8];
        g_srcP[p] = s;
        g_dstP[p] = d;
    }
}

// ---------------- per-node head logits (tiled): L[n][m] = xhat[n]@U[m] ----------------
// 128 nodes/block, BN folded into U' = U*sc and constant cU[m] = sum_k sh[k]*U[m][k].
__global__ void __launch_bounds__(256) k_L(const float* __restrict__ X,
                                           const float* __restrict__ U, int use_bn) {
    __shared__ __align__(16) float Xs[128][68];
    __shared__ __align__(16) float Us[4][64];
    __shared__ float cU[4];
    int tid = threadIdx.x;
    int nb = blockIdx.x * 128;
    const float* Xp = X ? X : g_H;

    // stage U with scale folded
    {
        int m = tid >> 6, k = tid & 63;
        float sck = use_bn ? g_scale[k] : 1.f;
        Us[m][k] = U[tid] * sck;
    }
    if (tid < 4) {
        float c = 0.f;
        if (use_bn) {
            for (int k = 0; k < 64; k++) c = fmaf(g_shift[k], U[tid * 64 + k], c);
        }
        cU[tid] = c;
    }
    // stage X tile coalesced (raw copy; 2048 float4s, 8 per thread)
    #pragma unroll
    for (int it = 0; it < 8; it++) {
        int idx4 = it * 256 + tid;
        int r = idx4 >> 4;
        int c4 = (idx4 & 15) << 2;
        int node = nb + r;
        float4 v = make_float4(0.f, 0.f, 0.f, 0.f);
        if (node < NN) v = *(const float4*)(Xp + (size_t)node * CH + c4);
        *(float4*)&Xs[r][c4] = v;
    }
    __syncthreads();

    // compute: thread -> (node r, head pair m0)
    int r = tid >> 1;
    int m0 = (tid & 1) * 2;
    float acc0 = cU[m0], acc1 = cU[m0 + 1];
    #pragma unroll
    for (int k = 0; k < 64; k += 4) {
        float4 xv = *(const float4*)&Xs[r][k];
        float4 u0 = *(const float4*)&Us[m0][k];
        float4 u1 = *(const float4*)&Us[m0 + 1][k];
        acc0 = fmaf(xv.x, u0.x, fmaf(xv.y, u0.y, fmaf(xv.z, u0.z, fmaf(xv.w, u0.w, acc0))));
        acc1 = fmaf(xv.x, u1.x, fmaf(xv.y, u1.y, fmaf(xv.z, u1.z, fmaf(xv.w, u1.w, acc1))));
    }
    int node = nb + r;
    if (node < NN) {
        *(float2*)(g_L + (size_t)node * 4 + m0) = make_float2(acc0, acc1);
    }
}

// ---------------- per-edge attention in CSR order (2 edges/thread) + fused W permute ----------------
__global__ void k_attn(const float* __restrict__ cc, const float* __restrict__ W) {
    int g = blockIdx.x * blockDim.x + threadIdx.x;
    if (blockIdx.x < 64) {
        int idx = blockIdx.x * 256 + threadIdx.x;   // 0..16383
        int r = idx >> 6;   // W row = m*64+o
        int c = idx & 63;   // channel
        int m = r >> 6;
        int o = r & 63;
        g_Wp[(c * 4 + m) * CH + o] = W[idx];
    }
    int p = 2 * g;
    if (p >= NE) return;
    int2 sp = *(const int2*)(g_srcP + p);
    int2 dp = *(const int2*)(g_dstP + p);
    float c0 = cc[0], c1 = cc[1], c2 = cc[2], c3 = cc[3];

    float4 ls0 = *(const float4*)(g_L + (size_t)sp.x * 4);
    float4 ld0 = *(const float4*)(g_L + (size_t)dp.x * 4);
    float4 ls1 = *(const float4*)(g_L + (size_t)sp.y * 4);
    float4 ld1 = *(const float4*)(g_L + (size_t)dp.y * 4);

    {
        float l0 = ld0.x - ls0.x + c0;
        float l1 = ld0.y - ls0.y + c1;
        float l2 = ld0.z - ls0.z + c2;
        float l3 = ld0.w - ls0.w + c3;
        float mx = fmaxf(fmaxf(l0, l1), fmaxf(l2, l3));
        float e0 = __expf(l0 - mx), e1 = __expf(l1 - mx), e2 = __expf(l2 - mx), e3 = __expf(l3 - mx);
        float inv = __fdividef(1.f, e0 + e1 + e2 + e3);
        *(float4*)(g_attnP + (size_t)p * 4) = make_float4(e0 * inv, e1 * inv, e2 * inv, e3 * inv);
    }
    {
        float l0 = ld1.x - ls1.x + c0;
        float l1 = ld1.y - ls1.y + c1;
        float l2 = ld1.z - ls1.z + c2;
        float l3 = ld1.w - ls1.w + c3;
        float mx = fmaxf(fmaxf(l0, l1), fmaxf(l2, l3));
        float e0 = __expf(l0 - mx), e1 = __expf(l1 - mx), e2 = __expf(l2 - mx), e3 = __expf(l3 - mx);
        float inv = __fdividef(1.f, e0 + e1 + e2 + e3);
        *(float4*)(g_attnP + (size_t)(p + 1) * 4) = make_float4(e0 * inv, e1 * inv, e2 * inv, e3 * inv);
    }
}

// ---------------- warp-per-node aggregation into Z (f32x2, depth-2 software pipeline) ----------------
__global__ void k_edge(const float* __restrict__ X, const float* __restrict__ cc, int use_bn) {
    int w = (blockIdx.x * blockDim.x + threadIdx.x) >> 5;
    int t = threadIdx.x & 31;
    if (w >= NN) return;
    const float* Xp = X ? X : g_H;
    int lo = g_rowptr[w] + g_boff[w >> 8];
    int hi = (w + 1 < NN) ? (g_rowptr[w + 1] + g_boff[(w + 1) >> 8]) : NE;
    float inv = __fdividef(1.f, (float)(hi - lo + 1));
    int k0 = 2 * t;
    float sc0 = 1.f, sc1 = 1.f, sh0 = 0.f, sh1 = 0.f;
    if (use_bn) { sc0 = g_scale[k0]; sc1 = g_scale[k0 + 1]; sh0 = g_shift[k0]; sh1 = g_shift[k0 + 1]; }

    // self-loop attention = softmax(c)
    float c0 = cc[0], c1 = cc[1], c2 = cc[2], c3 = cc[3];
    float mx = fmaxf(fmaxf(c0, c1), fmaxf(c2, c3));
    float e0 = __expf(c0 - mx), e1 = __expf(c1 - mx), e2 = __expf(c2 - mx), e3 = __expf(c3 - mx);
    float si = __fdividef(1.f, e0 + e1 + e2 + e3);
    ull W01 = pk2(e0 * si, e1 * si);
    ull W23 = pk2(e2 * si, e3 * si);

    float2 xv = *(const float2*)(Xp + (size_t)w * CH + k0);
    float xv0 = fmaf(xv.x, sc0, sh0);
    float xv1 = fmaf(xv.y, sc1, sh1);
    ull acc00 = mul2(pk2(xv0, xv0), W01);
    ull acc01 = mul2(pk2(xv0, xv0), W23);
    ull acc10 = mul2(pk2(xv1, xv1), W01);
    ull acc11 = mul2(pk2(xv1, xv1), W23);

    int i = lo;
    float2 x0, x1, x2, x3;
    if (i + 4 <= hi) {
        int s0 = g_srcP[i], s1 = g_srcP[i + 1], s2 = g_srcP[i + 2], s3 = g_srcP[i + 3];
        x0 = *(const float2*)(Xp + (size_t)s0 * CH + k0);
        x1 = *(const float2*)(Xp + (size_t)s1 * CH + k0);
        x2 = *(const float2*)(Xp + (size_t)s2 * CH + k0);
        x3 = *(const float2*)(Xp + (size_t)s3 * CH + k0);
    }
    for (; i + 4 <= hi; i += 4) {
        ulonglong2 A0 = *(const ulonglong2*)(g_attnP + (size_t)(i)     * 4);
        ulonglong2 A1 = *(const ulonglong2*)(g_attnP + (size_t)(i + 1) * 4);
        ulonglong2 A2 = *(const ulonglong2*)(g_attnP + (size_t)(i + 2) * 4);
        ulonglong2 A3 = *(const ulonglong2*)(g_attnP + (size_t)(i + 3) * 4);
        // depth-2 pipeline: issue next iteration's gathers before this iteration's FMAs
        float2 nx0 = x0, nx1 = x1, nx2 = x2, nx3 = x3;
        if (i + 8 <= hi) {
            int s0 = g_srcP[i + 4], s1 = g_srcP[i + 5], s2 = g_srcP[i + 6], s3 = g_srcP[i + 7];
            nx0 = *(const float2*)(Xp + (size_t)s0 * CH + k0);
            nx1 = *(const float2*)(Xp + (size_t)s1 * CH + k0);
            nx2 = *(const float2*)(Xp + (size_t)s2 * CH + k0);
            nx3 = *(const float2*)(Xp + (size_t)s3 * CH + k0);
        }

        float a0 = fmaf(x0.x, sc0, sh0), b0 = fmaf(x0.y, sc1, sh1);
        ull pa0 = pk2(a0, a0), pb0 = pk2(b0, b0);
        acc00 = fma2(pa0, A0.x, acc00); acc01 = fma2(pa0, A0.y, acc01);
        acc10 = fma2(pb0, A0.x, acc10); acc11 = fma2(pb0, A0.y, acc11);

        float a1 = fmaf(x1.x, sc0, sh0), b1 = fmaf(x1.y, sc1, sh1);
        ull pa1 = pk2(a1, a1), pb1 = pk2(b1, b1);
        acc00 = fma2(pa1, A1.x, acc00); acc01 = fma2(pa1, A1.y, acc01);
        acc10 = fma2(pb1, A1.x, acc10); acc11 = fma2(pb1, A1.y, acc11);

        float a2 = fmaf(x2.x, sc0, sh0), b2 = fmaf(x2.y, sc1, sh1);
        ull pa2 = pk2(a2, a2), pb2 = pk2(b2, b2);
        acc00 = fma2(pa2, A2.x, acc00); acc01 = fma2(pa2, A2.y, acc01);
        acc10 = fma2(pb2, A2.x, acc10); acc11 = fma2(pb2, A2.y, acc11);

        float a3 = fmaf(x3.x, sc0, sh0), b3 = fmaf(x3.y, sc1, sh1);
        ull pa3 = pk2(a3, a3), pb3 = pk2(b3, b3);
        acc00 = fma2(pa3, A3.x, acc00); acc01 = fma2(pa3, A3.y, acc01);
        acc10 = fma2(pb3, A3.x, acc10); acc11 = fma2(pb3, A3.y, acc11);

        x0 = nx0; x1 = nx1; x2 = nx2; x3 = nx3;
    }
    for (; i < hi; i++) {
        int s = g_srcP[i];
        ulonglong2 A = *(const ulonglong2*)(g_attnP + (size_t)i * 4);
        float2 x = *(const float2*)(Xp + (size_t)s * CH + k0);
        float a = fmaf(x.x, sc0, sh0), b = fmaf(x.y, sc1, sh1);
        ull pa = pk2(a, a), pb = pk2(b, b);
        acc00 = fma2(pa, A.x, acc00); acc01 = fma2(pa, A.y, acc01);
        acc10 = fma2(pb, A.x, acc10); acc11 = fma2(pb, A.y, acc11);
    }

    ull iv = pk2(inv, inv);
    ulonglong2 r0, r1;
    r0.x = mul2(acc00, iv); r0.y = mul2(acc01, iv);
    r1.x = mul2(acc10, iv); r1.y = mul2(acc11, iv);
    float* zr = g_Z + (size_t)w * KZ + k0 * 4;
    *(ulonglong2*)(zr)     = r0;
    *(ulonglong2*)(zr + 4) = r1;
}

// ---------------- dense GEMM (f32x2) + fence-free BN partial epilogue + deg re-zero ----------------
__global__ void __launch_bounds__(256) k_gemm(const float* __restrict__ b,
                                              float* __restrict__ extout, int relu,
                                              int do_bn, int zero_deg) {
    __shared__ __align__(16) float Xs[64 * 132];
    int tid = threadIdx.x;
    int nb = blockIdx.x * 128;
    float* out = extout ? extout : g_H;

    // re-zero g_deg for the next replay (runs after this replay's CSR build)
    if (zero_deg) {
        int i = blockIdx.x * 256 + tid;
        if (i < NN) g_deg[i] = 0;
    }

    ull acc[4][4];  // [node pair][col]
    #pragma unroll
    for (int p = 0; p < 4; p++)
        #pragma unroll
        for (int j = 0; j < 4; j++) acc[p][j] = 0ull;

    int tx = tid & 15;      // col group (4 cols)
    int ty = tid >> 4;      // node group (8 nodes)

    for (int kc = 0; kc < 4; kc++) {
        #pragma unroll
        for (int i = 0; i < 8; i++) {
            int f = i * 256 + tid;
            int nl = f >> 4;
            int kl = (f & 15) << 2;
            int node = nb + nl;
            float4 z = make_float4(0.f, 0.f, 0.f, 0.f);
            if (node < NN) z = *(const float4*)(g_Z + (size_t)node * KZ + kc * 64 + kl);
            Xs[(kl + 0) * 132 + nl] = z.x;
            Xs[(kl + 1) * 132 + nl] = z.y;
            Xs[(kl + 2) * 132 + nl] = z.z;
            Xs[(kl + 3) * 132 + nl] = z.w;
        }
        __syncthreads();
        #pragma unroll 8
        for (int kk = 0; kk < 64; kk++) {
            const float* xr = Xs + kk * 132 + ty * 8;
            ulonglong2 xa = *(const ulonglong2*)xr;
            ulonglong2 xb = *(const ulonglong2*)(xr + 4);
            float4 wv = *(const float4*)(g_Wp + (size_t)(kc * 64 + kk) * CH + tx * 4);
            ull w0 = pk2(wv.x, wv.x), w1 = pk2(wv.y, wv.y);
            ull w2 = pk2(wv.z, wv.z), w3 = pk2(wv.w, wv.w);
            acc[0][0] = fma2(xa.x, w0, acc[0][0]); acc[0][1] = fma2(xa.x, w1, acc[0][1]);
            acc[0][2] = fma2(xa.x, w2, acc[0][2]); acc[0][3] = fma2(xa.x, w3, acc[0][3]);
            acc[1][0] = fma2(xa.y, w0, acc[1][0]); acc[1][1] = fma2(xa.y, w1, acc[1][1]);
            acc[1][2] = fma2(xa.y, w2, acc[1][2]); acc[1][3] = fma2(xa.y, w3, acc[1][3]);
            acc[2][0] = fma2(xb.x, w0, acc[2][0]); acc[2][1] = fma2(xb.x, w1, acc[2][1]);
            acc[2][2] = fma2(xb.x, w2, acc[2][2]); acc[2][3] = fma2(xb.x, w3, acc[2][3]);
            acc[3][0] = fma2(xb.y, w0, acc[3][0]); acc[3][1] = fma2(xb.y, w1, acc[3][1]);
            acc[3][2] = fma2(xb.y, w2, acc[3][2]); acc[3][3] = fma2(xb.y, w3, acc[3][3]);
        }
        __syncthreads();
    }

    float4 bv = *(const float4*)(b + tx * 4);
    float s[4] = {0.f, 0.f, 0.f, 0.f};
    float q[4] = {0.f, 0.f, 0.f, 0.f};
    #pragma unroll
    for (int p = 0; p < 4; p++) {
        float lo0, hi0, lo1, hi1, lo2, hi2, lo3, hi3;
        upk2(lo0, hi0, acc[p][0]);
        upk2(lo1, hi1, acc[p][1]);
        upk2(lo2, hi2, acc[p][2]);
        upk2(lo3, hi3, acc[p][3]);
        int n0 = nb + ty * 8 + 2 * p;
        if (n0 < NN) {
            float4 r = make_float4(lo0 + bv.x, lo1 + bv.y, lo2 + bv.z, lo3 + bv.w);
            if (relu) {
                r.x = fmaxf(r.x, 0.f); r.y = fmaxf(r.y, 0.f);
                r.z = fmaxf(r.z, 0.f); r.w = fmaxf(r.w, 0.f);
            }
            *(float4*)(out + (size_t)n0 * CH + tx * 4) = r;
            s[0] += r.x; s[1] += r.y; s[2] += r.z; s[3] += r.w;
            q[0] = fmaf(r.x, r.x, q[0]); q[1] = fmaf(r.y, r.y, q[1]);
            q[2] = fmaf(r.z, r.z, q[2]); q[3] = fmaf(r.w, r.w, q[3]);
        }
        int n1 = n0 + 1;
        if (n1 < NN) {
            float4 r = make_float4(hi0 + bv.x, hi1 + bv.y, hi2 + bv.z, hi3 + bv.w);
            if (relu) {
                r.x = fmaxf(r.x, 0.f); r.y = fmaxf(r.y, 0.f);
                r.z = fmaxf(r.z, 0.f); r.w = fmaxf(r.w, 0.f);
            }
            *(float4*)(out + (size_t)n1 * CH + tx * 4) = r;
            s[0] += r.x; s[1] += r.y; s[2] += r.z; s[3] += r.w;
            q[0] = fmaf(r.x, r.x, q[0]); q[1] = fmaf(r.y, r.y, q[1]);
            q[2] = fmaf(r.z, r.z, q[2]); q[3] = fmaf(r.w, r.w, q[3]);
        }
    }

    if (!do_bn) return;
    // per-block BN partials from live registers — visible at kernel boundary, NO fence
    #pragma unroll
    for (int j = 0; j < 4; j++) {
        Xs[ty * 64 + tx * 4 + j]        = s[j];
        Xs[1024 + ty * 64 + tx * 4 + j] = q[j];
    }
    __syncthreads();
    if (tid < 64) {
        float S = 0.f, Q = 0.f;
        #pragma unroll
        for (int y = 0; y < 16; y++) {
            S += Xs[y * 64 + tid];
            Q += Xs[1024 + y * 64 + tid];
        }
        g_bnp[blockIdx.x * 64 + tid]  = S;
        g_bnp2[blockIdx.x * 64 + tid] = Q;
    }
}

// ---------------- BN final: reduce 235 block partials (4-way parallel) ----------------
__global__ void k_bnfinal(const float* __restrict__ g, const float* __restrict__ bt) {
    int ch = threadIdx.x & 63;
    int rg = threadIdx.x >> 6;   // 0..3
    float s = 0.f, s2 = 0.f;
    for (int blk = rg; blk < GEMM_BLOCKS; blk += 4) {
        s  += g_bnp[blk * 64 + ch];
        s2 += g_bnp2[blk * 64 + ch];
    }
    __shared__ float sh[4][64], sh2[4][64];
    sh[rg][ch] = s; sh2[rg][ch] = s2;
    __syncthreads();
    if (rg == 0) {
        s  = sh[0][ch]  + sh[1][ch]  + sh[2][ch]  + sh[3][ch];
        s2 = sh2[0][ch] + sh2[1][ch] + sh2[2][ch] + sh2[3][ch];
        float mu = s / (float)NN;
        float var = s2 / (float)NN - mu * mu;
        float sc = g[ch] * rsqrtf(var + 1e-5f);
        g_scale[ch] = sc;
        g_shift[ch] = bt[ch] - mu * sc;
    }
}

// ---------------- launch ----------------
extern "C" void kernel_launch(void* const* d_in, const int* in_sizes, int n_in,
                              void* d_out, int out_size) {
    const float* x    = (const float*)d_in[0];
    const int*   ei   = (const int*)d_in[1];      // edge_index: int32
    const float* W0   = (const float*)d_in[2];
    const float* U0   = (const float*)d_in[3];
    const float* c0   = (const float*)d_in[4];
    const float* b0   = (const float*)d_in[5];
    const float* g0   = (const float*)d_in[6];
    const float* bt0  = (const float*)d_in[7];
    const float* W1   = (const float*)d_in[8];
    const float* U1   = (const float*)d_in[9];
    const float* c1   = (const float*)d_in[10];
    const float* b1   = (const float*)d_in[11];
    const float* g1   = (const float*)d_in[12];
    const float* bt1  = (const float*)d_in[13];
    const float* W2   = (const float*)d_in[14];
    const float* U2   = (const float*)d_in[15];
    const float* c2   = (const float*)d_in[16];
    const float* b2   = (const float*)d_in[17];
    const int* srcE = ei;
    const int* dstE = ei + NE;
    float* out = (float*)d_out;

    const int GB_E  = (NE + 255) / 256;          // 1875
    const int GB_E2 = (NE / 2 + 255) / 256;      // 938 (2 edges/thread)
    const int GB_N  = SCAN_BLOCKS;               // 118
    const int GB_W  = NN / 8;                    // 3750 (warp per node, exact)
    const int GB_G  = GEMM_BLOCKS;               // 235
    const int GB_L  = (NN + 127) / 128;          // 235 (tiled k_L)

    // CSR build: 3 launches (deg pre-zeroed by module load / previous replay's gemm L0)
    k_count<<<GB_E2, 256>>>(dstE);
    k_scan<<<GB_N, 256>>>();
    k_scatter<<<GB_E, 256>>>(srcE, dstE);

    // ---- layer 0 ----
    k_L<<<GB_L, 256>>>(x, U0, 0);
    k_attn<<<GB_E2, 256>>>(c0, W0);
    k_edge<<<GB_W, 256>>>(x, c0, 0);
    k_gemm<<<GB_G, 256>>>(b0, nullptr, 1, 1, 1);   // +bn partials, +deg re-zero
    k_bnfinal<<<1, 256>>>(g0, bt0);

    // ---- layer 1 ----
    k_L<<<GB_L, 256>>>(nullptr, U1, 1);
    k_attn<<<GB_E2, 256>>>(c1, W1);
    k_edge<<<GB_W, 256>>>(nullptr, c1, 1);
    k_gemm<<<GB_G, 256>>>(b1, nullptr, 1, 1, 0);
    k_bnfinal<<<1, 256>>>(g1, bt1);

    // ---- layer 2 ----
    k_L<<<GB_L, 256>>>(nullptr, U2, 1);
    k_attn<<<GB_E2, 256>>>(c2, W2);
    k_edge<<<GB_W, 256>>>(nullptr, c2, 1);
    k_gemm<<<GB_G, 256>>>(b2, out, 0, 0, 0);

    (void)in_sizes; (void)n_in; (void)out_size;
}

// round 16
// speedup vs baseline: 1.0029x; 1.0010x over previous
#include <cuda_runtime.h>

#define NN 30000
#define NE 480000
#define CH 64
#define NHEADS 4
#define KZ 256          // 64 channels x 4 heads
#define SCAN_BLOCKS ((NN + 255) / 256)   // 118
#define GEMM_BLOCKS ((NN + 127) / 128)   // 235

typedef unsigned long long ull;

// ---------------- f32x2 helpers (sm_103a packed fp32 pipe) ----------------
__device__ __forceinline__ ull pk2(float lo, float hi) {
    ull r;
    asm("mov.b64 %0, {%1, %2};" : "=l"(r) : "f"(lo), "f"(hi));
    return r;
}
__device__ __forceinline__ void upk2(float& lo, float& hi, ull v) {
    asm("mov.b64 {%0, %1}, %2;" : "=f"(lo), "=f"(hi) : "l"(v));
}
__device__ __forceinline__ ull fma2(ull a, ull b, ull c) {
    ull d;
    asm("fma.rn.f32x2 %0, %1, %2, %3;" : "=l"(d) : "l"(a), "l"(b), "l"(c));
    return d;
}
__device__ __forceinline__ ull mul2(ull a, ull b) {
    ull d;
    asm("mul.rn.f32x2 %0, %1, %2;" : "=l"(d) : "l"(a), "l"(b));
    return d;
}

// ---------------- scratch (device globals; no allocations allowed) ----------------
__device__ __align__(16) float g_L[NN * 4];        // per-node head logits
__device__ __align__(16) float g_attnP[NE * 4];    // per-edge attention, CSR order
__device__ __align__(16) float g_Z[NN * KZ];       // aggregated weighted features [node][c*4+m]
__device__ __align__(16) float g_H[NN * CH];       // relu(conv) output between layers
__device__ __align__(16) float g_Wp[KZ * CH];      // permuted weight for current layer
__device__ int   g_deg[NN];                        // zeroed at module load; re-zeroed by k_gemm L0
__device__ int   g_rowptr[NN];                     // block-local exclusive prefix
__device__ int   g_wptr[NN];                       // block-local write cursor
__device__ int   g_srcP[NE];                       // src node per CSR position
__device__ int   g_dstP[NE];                       // dst node per CSR position
__device__ int   g_bsum[SCAN_BLOCKS];
__device__ int   g_boff[SCAN_BLOCKS];              // per-256-node-block global offset
__device__ int   g_ctr;                            // scan completion counter (self-resetting)
__device__ float g_bnp[GEMM_BLOCKS * CH];
__device__ float g_bnp2[GEMM_BLOCKS * CH];
__device__ float g_scale[CH];
__device__ float g_shift[CH];

// ---------------- CSR build ----------------
__global__ void k_count(const int* __restrict__ dstE) {
    int g = blockIdx.x * blockDim.x + threadIdx.x;
    int e = 2 * g;
    if (e < NE) {
        int2 d = *(const int2*)(dstE + e);
        atomicAdd(&g_deg[d.x], 1);
        atomicAdd(&g_deg[d.y], 1);
    }
}

// fused scan: per-block local scan; last block scans the 118 block sums.
__global__ void k_scan() {
    int b = blockIdx.x, t = threadIdx.x;
    int i = b * 256 + t;
    int v = (i < NN) ? g_deg[i] : 0;
    int lane = t & 31, wid = t >> 5;
    int x = v;
    #pragma unroll
    for (int off = 1; off < 32; off <<= 1) {
        int y = __shfl_up_sync(0xFFFFFFFFu, x, off);
        if (lane >= off) x += y;
    }
    __shared__ int wsum[8];
    __shared__ int sIsLast;
    if (lane == 31) wsum[wid] = x;
    __syncthreads();
    if (wid == 0) {
        int s = (lane < 8) ? wsum[lane] : 0;
        #pragma unroll
        for (int off = 1; off < 8; off <<= 1) {
            int y = __shfl_up_sync(0xFFFFFFFFu, s, off);
            if (lane >= off) s += y;
        }
        if (lane < 8) wsum[lane] = s;   // inclusive warp sums
    }
    __syncthreads();
    int base = (wid > 0) ? wsum[wid - 1] : 0;
    int excl = base + x - v;
    if (i < NN) { g_rowptr[i] = excl; g_wptr[i] = excl; }
    if (t == 255) g_bsum[b] = base + x;

    // last block scans the block sums into g_boff
    __threadfence();   // tiny kernel: L1 flush harmless here
    __syncthreads();
    if (t == 0) sIsLast = (atomicAdd(&g_ctr, 1) == (int)gridDim.x - 1);
    __syncthreads();
    if (sIsLast) {
        int v2 = (t < SCAN_BLOCKS) ? g_bsum[t] : 0;
        int x2 = v2;
        #pragma unroll
        for (int off = 1; off < 32; off <<= 1) {
            int y = __shfl_up_sync(0xFFFFFFFFu, x2, off);
            if (lane >= off) x2 += y;
        }
        __shared__ int ws2[8];
        if (lane == 31) ws2[wid] = x2;
        __syncthreads();
        if (t == 0) {
            int a = 0;
            #pragma unroll
            for (int wv = 0; wv < 8; wv++) { int tmp = ws2[wv]; ws2[wv] = a; a += tmp; }
            g_ctr = 0;   // self-reset for next replay
        }
        __syncthreads();
        if (t < SCAN_BLOCKS) g_boff[t] = ws2[wid] + x2 - v2;
    }
}

__global__ void k_scatter(const int* __restrict__ srcE, const int* __restrict__ dstE) {
    int e = blockIdx.x * blockDim.x + threadIdx.x;
    if (e < NE) {
        int s = srcE[e];
        int d = dstE[e];
        int p = atomicAdd(&g_wptr[d], 1) + g_boff[d >> 8];
        g_srcP[p] = s;
        g_dstP[p] = d;
    }
}

// ---------------- per-node head logits (tiled): L[n][m] = xhat[n]@U[m] ----------------
// 128 nodes/block, BN folded into U' = U*sc and constant cU[m] = sum_k sh[k]*U[m][k].
__global__ void __launch_bounds__(256) k_L(const float* __restrict__ X,
                                           const float* __restrict__ U, int use_bn) {
    __shared__ __align__(16) float Xs[128][68];
    __shared__ __align__(16) float Us[4][64];
    __shared__ float cU[4];
    int tid = threadIdx.x;
    int nb = blockIdx.x * 128;
    const float* Xp = X ? X : g_H;

    // stage U with scale folded
    {
        int m = tid >> 6, k = tid & 63;
        float sck = use_bn ? g_scale[k] : 1.f;
        Us[m][k] = U[tid] * sck;
    }
    if (tid < 4) {
        float c = 0.f;
        if (use_bn) {
            for (int k = 0; k < 64; k++) c = fmaf(g_shift[k], U[tid * 64 + k], c);
        }
        cU[tid] = c;
    }
    // stage X tile coalesced (raw copy; 2048 float4s, 8 per thread)
    #pragma unroll
    for (int it = 0; it < 8; it++) {
        int idx4 = it * 256 + tid;
        int r = idx4 >> 4;
        int c4 = (idx4 & 15) << 2;
        int node = nb + r;
        float4 v = make_float4(0.f, 0.f, 0.f, 0.f);
        if (node < NN) v = *(const float4*)(Xp + (size_t)node * CH + c4);
        *(float4*)&Xs[r][c4] = v;
    }
    __syncthreads();

    // compute: thread -> (node r, head pair m0)
    int r = tid >> 1;
    int m0 = (tid & 1) * 2;
    float acc0 = cU[m0], acc1 = cU[m0 + 1];
    #pragma unroll
    for (int k = 0; k < 64; k += 4) {
        float4 xv = *(const float4*)&Xs[r][k];
        float4 u0 = *(const float4*)&Us[m0][k];
        float4 u1 = *(const float4*)&Us[m0 + 1][k];
        acc0 = fmaf(xv.x, u0.x, fmaf(xv.y, u0.y, fmaf(xv.z, u0.z, fmaf(xv.w, u0.w, acc0))));
        acc1 = fmaf(xv.x, u1.x, fmaf(xv.y, u1.y, fmaf(xv.z, u1.z, fmaf(xv.w, u1.w, acc1))));
    }
    int node = nb + r;
    if (node < NN) {
        *(float2*)(g_L + (size_t)node * 4 + m0) = make_float2(acc0, acc1);
    }
}

// ---------------- per-edge attention in CSR order (2 edges/thread) + fused W permute ----------------
__global__ void k_attn(const float* __restrict__ cc, const float* __restrict__ W) {
    int g = blockIdx.x * blockDim.x + threadIdx.x;
    if (blockIdx.x < 64) {
        int idx = blockIdx.x * 256 + threadIdx.x;   // 0..16383
        int r = idx >> 6;   // W row = m*64+o
        int c = idx & 63;   // channel
        int m = r >> 6;
        int o = r & 63;
        g_Wp[(c * 4 + m) * CH + o] = W[idx];
    }
    int p = 2 * g;
    if (p >= NE) return;
    int2 sp = *(const int2*)(g_srcP + p);
    int2 dp = *(const int2*)(g_dstP + p);
    float c0 = cc[0], c1 = cc[1], c2 = cc[2], c3 = cc[3];

    float4 ls0 = *(const float4*)(g_L + (size_t)sp.x * 4);
    float4 ld0 = *(const float4*)(g_L + (size_t)dp.x * 4);
    float4 ls1 = *(const float4*)(g_L + (size_t)sp.y * 4);
    float4 ld1 = *(const float4*)(g_L + (size_t)dp.y * 4);

    {
        float l0 = ld0.x - ls0.x + c0;
        float l1 = ld0.y - ls0.y + c1;
        float l2 = ld0.z - ls0.z + c2;
        float l3 = ld0.w - ls0.w + c3;
        float mx = fmaxf(fmaxf(l0, l1), fmaxf(l2, l3));
        float e0 = __expf(l0 - mx), e1 = __expf(l1 - mx), e2 = __expf(l2 - mx), e3 = __expf(l3 - mx);
        float inv = __fdividef(1.f, e0 + e1 + e2 + e3);
        *(float4*)(g_attnP + (size_t)p * 4) = make_float4(e0 * inv, e1 * inv, e2 * inv, e3 * inv);
    }
    {
        float l0 = ld1.x - ls1.x + c0;
        float l1 = ld1.y - ls1.y + c1;
        float l2 = ld1.z - ls1.z + c2;
        float l3 = ld1.w - ls1.w + c3;
        float mx = fmaxf(fmaxf(l0, l1), fmaxf(l2, l3));
        float e0 = __expf(l0 - mx), e1 = __expf(l1 - mx), e2 = __expf(l2 - mx), e3 = __expf(l3 - mx);
        float inv = __fdividef(1.f, e0 + e1 + e2 + e3);
        *(float4*)(g_attnP + (size_t)(p + 1) * 4) = make_float4(e0 * inv, e1 * inv, e2 * inv, e3 * inv);
    }
}

// ---------------- warp-per-node aggregation into Z (f32x2, depth-2 software pipeline) ----------------
__global__ void k_edge(const float* __restrict__ X, const float* __restrict__ cc, int use_bn) {
    int w = (blockIdx.x * blockDim.x + threadIdx.x) >> 5;
    int t = threadIdx.x & 31;
    if (w >= NN) return;
    const float* Xp = X ? X : g_H;
    int lo = g_rowptr[w] + g_boff[w >> 8];
    int hi = (w + 1 < NN) ? (g_rowptr[w + 1] + g_boff[(w + 1) >> 8]) : NE;
    float inv = __fdividef(1.f, (float)(hi - lo + 1));
    int k0 = 2 * t;
    float sc0 = 1.f, sc1 = 1.f, sh0 = 0.f, sh1 = 0.f;
    if (use_bn) { sc0 = g_scale[k0]; sc1 = g_scale[k0 + 1]; sh0 = g_shift[k0]; sh1 = g_shift[k0 + 1]; }

    // self-loop attention = softmax(c)
    float c0 = cc[0], c1 = cc[1], c2 = cc[2], c3 = cc[3];
    float mx = fmaxf(fmaxf(c0, c1), fmaxf(c2, c3));
    float e0 = __expf(c0 - mx), e1 = __expf(c1 - mx), e2 = __expf(c2 - mx), e3 = __expf(c3 - mx);
    float si = __fdividef(1.f, e0 + e1 + e2 + e3);
    ull W01 = pk2(e0 * si, e1 * si);
    ull W23 = pk2(e2 * si, e3 * si);

    float2 xv = *(const float2*)(Xp + (size_t)w * CH + k0);
    float xv0 = fmaf(xv.x, sc0, sh0);
    float xv1 = fmaf(xv.y, sc1, sh1);
    ull acc00 = mul2(pk2(xv0, xv0), W01);
    ull acc01 = mul2(pk2(xv0, xv0), W23);
    ull acc10 = mul2(pk2(xv1, xv1), W01);
    ull acc11 = mul2(pk2(xv1, xv1), W23);

    int i = lo;
    float2 x0, x1, x2, x3;
    if (i + 4 <= hi) {
        int s0 = g_srcP[i], s1 = g_srcP[i + 1], s2 = g_srcP[i + 2], s3 = g_srcP[i + 3];
        x0 = *(const float2*)(Xp + (size_t)s0 * CH + k0);
        x1 = *(const float2*)(Xp + (size_t)s1 * CH + k0);
        x2 = *(const float2*)(Xp + (size_t)s2 * CH + k0);
        x3 = *(const float2*)(Xp + (size_t)s3 * CH + k0);
    }
    for (; i + 4 <= hi; i += 4) {
        ulonglong2 A0 = *(const ulonglong2*)(g_attnP + (size_t)(i)     * 4);
        ulonglong2 A1 = *(const ulonglong2*)(g_attnP + (size_t)(i + 1) * 4);
        ulonglong2 A2 = *(const ulonglong2*)(g_attnP + (size_t)(i + 2) * 4);
        ulonglong2 A3 = *(const ulonglong2*)(g_attnP + (size_t)(i + 3) * 4);
        // depth-2 pipeline: issue next iteration's gathers before this iteration's FMAs
        float2 nx0 = x0, nx1 = x1, nx2 = x2, nx3 = x3;
        if (i + 8 <= hi) {
            int s0 = g_srcP[i + 4], s1 = g_srcP[i + 5], s2 = g_srcP[i + 6], s3 = g_srcP[i + 7];
            nx0 = *(const float2*)(Xp + (size_t)s0 * CH + k0);
            nx1 = *(const float2*)(Xp + (size_t)s1 * CH + k0);
            nx2 = *(const float2*)(Xp + (size_t)s2 * CH + k0);
            nx3 = *(const float2*)(Xp + (size_t)s3 * CH + k0);
        }

        float a0 = fmaf(x0.x, sc0, sh0), b0 = fmaf(x0.y, sc1, sh1);
        ull pa0 = pk2(a0, a0), pb0 = pk2(b0, b0);
        acc00 = fma2(pa0, A0.x, acc00); acc01 = fma2(pa0, A0.y, acc01);
        acc10 = fma2(pb0, A0.x, acc10); acc11 = fma2(pb0, A0.y, acc11);

        float a1 = fmaf(x1.x, sc0, sh0), b1 = fmaf(x1.y, sc1, sh1);
        ull pa1 = pk2(a1, a1), pb1 = pk2(b1, b1);
        acc00 = fma2(pa1, A1.x, acc00); acc01 = fma2(pa1, A1.y, acc01);
        acc10 = fma2(pb1, A1.x, acc10); acc11 = fma2(pb1, A1.y, acc11);

        float a2 = fmaf(x2.x, sc0, sh0), b2 = fmaf(x2.y, sc1, sh1);
        ull pa2 = pk2(a2, a2), pb2 = pk2(b2, b2);
        acc00 = fma2(pa2, A2.x, acc00); acc01 = fma2(pa2, A2.y, acc01);
        acc10 = fma2(pb2, A2.x, acc10); acc11 = fma2(pb2, A2.y, acc11);

        float a3 = fmaf(x3.x, sc0, sh0), b3 = fmaf(x3.y, sc1, sh1);
        ull pa3 = pk2(a3, a3), pb3 = pk2(b3, b3);
        acc00 = fma2(pa3, A3.x, acc00); acc01 = fma2(pa3, A3.y, acc01);
        acc10 = fma2(pb3, A3.x, acc10); acc11 = fma2(pb3, A3.y, acc11);

        x0 = nx0; x1 = nx1; x2 = nx2; x3 = nx3;
    }
    for (; i < hi; i++) {
        int s = g_srcP[i];
        ulonglong2 A = *(const ulonglong2*)(g_attnP + (size_t)i * 4);
        float2 x = *(const float2*)(Xp + (size_t)s * CH + k0);
        float a = fmaf(x.x, sc0, sh0), b = fmaf(x.y, sc1, sh1);
        ull pa = pk2(a, a), pb = pk2(b, b);
        acc00 = fma2(pa, A.x, acc00); acc01 = fma2(pa, A.y, acc01);
        acc10 = fma2(pb, A.x, acc10); acc11 = fma2(pb, A.y, acc11);
    }

    ull iv = pk2(inv, inv);
    ulonglong2 r0, r1;
    r0.x = mul2(acc00, iv); r0.y = mul2(acc01, iv);
    r1.x = mul2(acc10, iv); r1.y = mul2(acc11, iv);
    float* zr = g_Z + (size_t)w * KZ + k0 * 4;
    *(ulonglong2*)(zr)     = r0;
    *(ulonglong2*)(zr + 4) = r1;
}

// ---------------- dense GEMM (f32x2) + fence-free BN partial epilogue + deg re-zero ----------------
__global__ void __launch_bounds__(256) k_gemm(const float* __restrict__ b,
                                              float* __restrict__ extout, int relu,
                                              int do_bn, int zero_deg) {
    __shared__ __align__(16) float Xs[64 * 132];
    int tid = threadIdx.x;
    int nb = blockIdx.x * 128;
    float* out = extout ? extout : g_H;

    // re-zero g_deg for the next replay (runs after this replay's CSR build)
    if (zero_deg) {
        int i = blockIdx.x * 256 + tid;
        if (i < NN) g_deg[i] = 0;
    }

    ull acc[4][4];  // [node pair][col]
    #pragma unroll
    for (int p = 0; p < 4; p++)
        #pragma unroll
        for (int j = 0; j < 4; j++) acc[p][j] = 0ull;

    int tx = tid & 15;      // col group (4 cols)
    int ty = tid >> 4;      // node group (8 nodes)

    for (int kc = 0; kc < 4; kc++) {
        #pragma unroll
        for (int i = 0; i < 8; i++) {
            int f = i * 256 + tid;
            int nl = f >> 4;
            int kl = (f & 15) << 2;
            int node = nb + nl;
            float4 z = make_float4(0.f, 0.f, 0.f, 0.f);
            if (node < NN) z = *(const float4*)(g_Z + (size_t)node * KZ + kc * 64 + kl);
            Xs[(kl + 0) * 132 + nl] = z.x;
            Xs[(kl + 1) * 132 + nl] = z.y;
            Xs[(kl + 2) * 132 + nl] = z.z;
            Xs[(kl + 3) * 132 + nl] = z.w;
        }
        __syncthreads();
        #pragma unroll 8
        for (int kk = 0; kk < 64; kk++) {
            const float* xr = Xs + kk * 132 + ty * 8;
            ulonglong2 xa = *(const ulonglong2*)xr;
            ulonglong2 xb = *(const ulonglong2*)(xr + 4);
            float4 wv = *(const float4*)(g_Wp + (size_t)(kc * 64 + kk) * CH + tx * 4);
            ull w0 = pk2(wv.x, wv.x), w1 = pk2(wv.y, wv.y);
            ull w2 = pk2(wv.z, wv.z), w3 = pk2(wv.w, wv.w);
            acc[0][0] = fma2(xa.x, w0, acc[0][0]); acc[0][1] = fma2(xa.x, w1, acc[0][1]);
            acc[0][2] = fma2(xa.x, w2, acc[0][2]); acc[0][3] = fma2(xa.x, w3, acc[0][3]);
            acc[1][0] = fma2(xa.y, w0, acc[1][0]); acc[1][1] = fma2(xa.y, w1, acc[1][1]);
            acc[1][2] = fma2(xa.y, w2, acc[1][2]); acc[1][3] = fma2(xa.y, w3, acc[1][3]);
            acc[2][0] = fma2(xb.x, w0, acc[2][0]); acc[2][1] = fma2(xb.x, w1, acc[2][1]);
            acc[2][2] = fma2(xb.x, w2, acc[2][2]); acc[2][3] = fma2(xb.x, w3, acc[2][3]);
            acc[3][0] = fma2(xb.y, w0, acc[3][0]); acc[3][1] = fma2(xb.y, w1, acc[3][1]);
            acc[3][2] = fma2(xb.y, w2, acc[3][2]); acc[3][3] = fma2(xb.y, w3, acc[3][3]);
        }
        __syncthreads();
    }

    float4 bv = *(const float4*)(b + tx * 4);
    float s[4] = {0.f, 0.f, 0.f, 0.f};
    float q[4] = {0.f, 0.f, 0.f, 0.f};
    #pragma unroll
    for (int p = 0; p < 4; p++) {
        float lo0, hi0, lo1, hi1, lo2, hi2, lo3, hi3;
        upk2(lo0, hi0, acc[p][0]);
        upk2(lo1, hi1, acc[p][1]);
        upk2(lo2, hi2, acc[p][2]);
        upk2(lo3, hi3, acc[p][3]);
        int n0 = nb + ty * 8 + 2 * p;
        if (n0 < NN) {
            float4 r = make_float4(lo0 + bv.x, lo1 + bv.y, lo2 + bv.z, lo3 + bv.w);
            if (relu) {
                r.x = fmaxf(r.x, 0.f); r.y = fmaxf(r.y, 0.f);
                r.z = fmaxf(r.z, 0.f); r.w = fmaxf(r.w, 0.f);
            }
            *(float4*)(out + (size_t)n0 * CH + tx * 4) = r;
            s[0] += r.x; s[1] += r.y; s[2] += r.z; s[3] += r.w;
            q[0] = fmaf(r.x, r.x, q[0]); q[1] = fmaf(r.y, r.y, q[1]);
            q[2] = fmaf(r.z, r.z, q[2]); q[3] = fmaf(r.w, r.w, q[3]);
        }
        int n1 = n0 + 1;
        if (n1 < NN) {
            float4 r = make_float4(hi0 + bv.x, hi1 + bv.y, hi2 + bv.z, hi3 + bv.w);
            if (relu) {
                r.x = fmaxf(r.x, 0.f); r.y = fmaxf(r.y, 0.f);
                r.z = fmaxf(r.z, 0.f); r.w = fmaxf(r.w, 0.f);
            }
            *(float4*)(out + (size_t)n1 * CH + tx * 4) = r;
            s[0] += r.x; s[1] += r.y; s[2] += r.z; s[3] += r.w;
            q[0] = fmaf(r.x, r.x, q[0]); q[1] = fmaf(r.y, r.y, q[1]);
            q[2] = fmaf(r.z, r.z, q[2]); q[3] = fmaf(r.w, r.w, q[3]);
        }
    }

    if (!do_bn) return;
    // per-block BN partials from live registers — visible at kernel boundary, NO fence
    #pragma unroll
    for (int j = 0; j < 4; j++) {
        Xs[ty * 64 + tx * 4 + j]        = s[j];
        Xs[1024 + ty * 64 + tx * 4 + j] = q[j];
    }
    __syncthreads();
    if (tid < 64) {
        float S = 0.f, Q = 0.f;
        #pragma unroll
        for (int y = 0; y < 16; y++) {
            S += Xs[y * 64 + tid];
            Q += Xs[1024 + y * 64 + tid];
        }
        g_bnp[blockIdx.x * 64 + tid]  = S;
        g_bnp2[blockIdx.x * 64 + tid] = Q;
    }
}

// ---------------- BN final: reduce 235 block partials (4-way parallel) ----------------
__global__ void k_bnfinal(const float* __restrict__ g, const float* __restrict__ bt) {
    int ch = threadIdx.x & 63;
    int rg = threadIdx.x >> 6;   // 0..3
    float s = 0.f, s2 = 0.f;
    for (int blk = rg; blk < GEMM_BLOCKS; blk += 4) {
        s  += g_bnp[blk * 64 + ch];
        s2 += g_bnp2[blk * 64 + ch];
    }
    __shared__ float sh[4][64], sh2[4][64];
    sh[rg][ch] = s; sh2[rg][ch] = s2;
    __syncthreads();
    if (rg == 0) {
        s  = sh[0][ch]  + sh[1][ch]  + sh[2][ch]  + sh[3][ch];
        s2 = sh2[0][ch] + sh2[1][ch] + sh2[2][ch] + sh2[3][ch];
        float mu = s / (float)NN;
        float var = s2 / (float)NN - mu * mu;
        float sc = g[ch] * rsqrtf(var + 1e-5f);
        g_scale[ch] = sc;
        g_shift[ch] = bt[ch] - mu * sc;
    }
}

// ---------------- launch ----------------
extern "C" void kernel_launch(void* const* d_in, const int* in_sizes, int n_in,
                              void* d_out, int out_size) {
    const float* x    = (const float*)d_in[0];
    const int*   ei   = (const int*)d_in[1];      // edge_index: int32
    const float* W0   = (const float*)d_in[2];
    const float* U0   = (const float*)d_in[3];
    const float* c0   = (const float*)d_in[4];
    const float* b0   = (const float*)d_in[5];
    const float* g0   = (const float*)d_in[6];
    const float* bt0  = (const float*)d_in[7];
    const float* W1   = (const float*)d_in[8];
    const float* U1   = (const float*)d_in[9];
    const float* c1   = (const float*)d_in[10];
    const float* b1   = (const float*)d_in[11];
    const float* g1   = (const float*)d_in[12];
    const float* bt1  = (const float*)d_in[13];
    const float* W2   = (const float*)d_in[14];
    const float* U2   = (const float*)d_in[15];
    const float* c2   = (const float*)d_in[16];
    const float* b2   = (const float*)d_in[17];
    const int* srcE = ei;
    const int* dstE = ei + NE;
    float* out = (float*)d_out;

    const int GB_E  = (NE + 255) / 256;          // 1875
    const int GB_E2 = (NE / 2 + 255) / 256;      // 938 (2 edges/thread)
    const int GB_N  = SCAN_BLOCKS;               // 118
    const int GB_W  = NN / 8;                    // 3750 (warp per node, exact)
    const int GB_G  = GEMM_BLOCKS;               // 235
    const int GB_L  = (NN + 127) / 128;          // 235 (tiled k_L)

    // CSR build: 3 launches (deg pre-zeroed by module load / previous replay's gemm L0)
    k_count<<<GB_E2, 256>>>(dstE);
    k_scan<<<GB_N, 256>>>();
    k_scatter<<<GB_E, 256>>>(srcE, dstE);

    // ---- layer 0 ----
    k_L<<<GB_L, 256>>>(x, U0, 0);
    k_attn<<<GB_E2, 256>>>(c0, W0);
    k_edge<<<GB_W, 256>>>(x, c0, 0);
    k_gemm<<<GB_G, 256>>>(b0, nullptr, 1, 1, 1);   // +bn partials, +deg re-zero
    k_bnfinal<<<1, 256>>>(g0, bt0);

    // ---- layer 1 ----
    k_L<<<GB_L, 256>>>(nullptr, U1, 1);
    k_attn<<<GB_E2, 256>>>(c1, W1);
    k_edge<<<GB_W, 256>>>(nullptr, c1, 1);
    k_gemm<<<GB_G, 256>>>(b1, nullptr, 1, 1, 0);
    k_bnfinal<<<1, 256>>>(g1, bt1);

    // ---- layer 2 ----
    k_L<<<GB_L, 256>>>(nullptr, U2, 1);
    k_attn<<<GB_E2, 256>>>(c2, W2);
    k_edge<<<GB_W, 256>>>(nullptr, c2, 1);
    k_gemm<<<GB_G, 256>>>(b2, out, 0, 0, 0);

    (void)in_sizes; (void)n_in; (void)out_size;
}